// round 2
// baseline (speedup 1.0000x reference)
#include <cuda_runtime.h>
#include <math.h>
#include <stdint.h>

#define BB 2
#define NN 100000
#define EE 400000
#define NODE_DIM 32
#define DD 64
#define H0 128
#define H1 64
#define TILE_E 64
#define SHP 66   // s_h row pitch in f32x2

// -------- device scratch --------
__device__ float g_hnodes[(size_t)BB * NN * DD];   // 51.2 MB
__device__ float g_sum[BB * DD];
__device__ int   g_cnt[BB];
__device__ int   g_mask_mode;                      // 0=u8, 1=i32, 2=f32

// fast accurate tanh: MUFU ex2 + rcp, abs err ~1e-7
__device__ __forceinline__ float ftanh(float x) {
    float e = __expf(2.0f * x);
    return 1.0f - __fdividef(2.0f, e + 1.0f);
}

__device__ __forceinline__ bool mask_at(const void* m, long long i, int mode) {
    if (mode == 1) return ((const int*)m)[i] != 0;
    if (mode == 2) return ((const float*)m)[i] != 0.0f;
    return ((const unsigned char*)m)[i] != 0;
}

// -------- init: zero accumulators + detect mask dtype --------
__global__ void k_init(const unsigned int* mask_words) {
    int t = threadIdx.x;
    if (t < BB * DD) g_sum[t] = 0.0f;
    if (t < BB) g_cnt[t] = 0;
    __shared__ int s_notint, s_notfl;
    if (t == 0) { s_notint = 0; s_notfl = 0; }
    __syncthreads();
    int ni = 0, nf = 0;
    for (int i = t; i < 1024; i += blockDim.x) {
        unsigned w = mask_words[i];
        if (w > 1u) ni = 1;
        if (w != 0u && w != 0x3F800000u) nf = 1;
    }
    if (ni) atomicOr(&s_notint, 1);
    if (nf) atomicOr(&s_notfl, 1);
    __syncthreads();
    if (t == 0) g_mask_mode = (!s_notint) ? 1 : ((!s_notfl) ? 2 : 0);
}

// -------- node MLP: h_nodes = tanh(nf @ Wn + bn) --------
__global__ void k_nodes(const float* __restrict__ nf,
                        const float* __restrict__ Wn,
                        const float* __restrict__ bn) {
    __shared__ float2 ws[NODE_DIM][32];
    __shared__ float2 bs[32];
    int tid = threadIdx.x, lane = tid & 31, w = tid >> 5;
    for (int i = tid; i < NODE_DIM * 32; i += blockDim.x) {
        int k = i >> 5, j = i & 31;
        ws[k][j] = make_float2(Wn[k * DD + j], Wn[k * DD + j + 32]);
    }
    if (tid < 32) bs[tid] = make_float2(bn[tid], bn[tid + 32]);
    __syncthreads();

    const int nrows = BB * NN;
    const int warps = (blockDim.x >> 5) * gridDim.x;
    for (int row = blockIdx.x * (blockDim.x >> 5) + w; row < nrows; row += warps) {
        float x = nf[(size_t)row * NODE_DIM + lane];
        float2 acc = bs[lane];
#pragma unroll
        for (int k = 0; k < NODE_DIM; k++) {
            float v = __shfl_sync(0xffffffffu, x, k);
            float2 wv = ws[k][lane];
            acc.x = fmaf(v, wv.x, acc.x);
            acc.y = fmaf(v, wv.y, acc.y);
        }
        float* o = g_hnodes + (size_t)row * DD;
        o[lane]      = ftanh(acc.x);
        o[lane + 32] = ftanh(acc.y);
    }
}

// -------- edge kernel --------
// dynamic smem layout (bytes):
//   [0, 32768)            float2 s_w[64][64]      (wsum, wdiff)[k][d]
//   [32768, 66560)        float2 s_h[64][SHP=66]  (hs, hd)[k][e]
//   [66560, 66816)        float  s_be[64]
//   [66816, 67328)        float  s_sum[128]
//   [67328, 67840)        int    s_ei[128]
//   [67840, 67848)        unsigned s_mask[2]
#define EDGE_SMEM 67968

#define FMA2(acc, a, b) asm("fma.rn.f32x2 %0, %1, %2, %0;" : "+l"(acc) : "l"(a), "l"(b))

__global__ void __launch_bounds__(128, 3) k_edges(
    const float* __restrict__ We, const float* __restrict__ be,
    const int* __restrict__ eidx, const void* __restrict__ mask,
    float* __restrict__ out_policy)
{
    extern __shared__ unsigned char dsm[];
    float2*   s_w    = (float2*)dsm;
    float2*   s_h    = (float2*)(dsm + 32768);
    float*    s_be   = (float*)(dsm + 66560);
    float*    s_sum  = (float*)(dsm + 66816);
    int*      s_ei   = (int*)(dsm + 67328);
    unsigned* s_mask = (unsigned*)(dsm + 67840);

    const int tid = threadIdx.x;
    const int lane = tid & 31, w = tid >> 5;
    const int mode = g_mask_mode;

    // (Wa+Wb, Wa-Wb) into smem once per persistent block
    for (int i = tid; i < 64 * 64; i += 128) {
        int k = i >> 6, d = i & 63;
        float a = We[k * 64 + d];
        float b = We[(64 + k) * 64 + d];
        s_w[i] = make_float2(a + b, a - b);
    }
    if (tid < 64) s_be[tid] = be[tid];
    if (tid < BB * DD) s_sum[tid] = 0.0f;

    // per-thread compute mapping
    const int el = lane & 7;              // edge group 0..7
    const int dl = lane >> 3;             // dim group within warp 0..3
    const int e0 = el * 8;                // 8 consecutive edges
    const int d0 = (w * 4 + dl) * 4;      // 4 consecutive dims

    int cnt0 = 0, cnt1 = 0;               // masked-edge counts (tid 0 only uses)

    const int tiles_per_b = EE / TILE_E;  // 6250
    const int ntiles = BB * tiles_per_b;  // 12500

    for (int tile = blockIdx.x; tile < ntiles; tile += gridDim.x) {
        const int b = tile / tiles_per_b;
        const long long eg = (long long)b * EE + (long long)(tile - b * tiles_per_b) * TILE_E;

        __syncthreads();   // protect s_ei/s_mask/s_h from previous tile readers
        s_ei[tid] = eidx[eg * 2 + tid];
        if (w < 2) {
            bool m = mask_at(mask, eg + w * 32 + lane, mode);
            unsigned bal = __ballot_sync(0xffffffffu, m);
            if (lane == 0) s_mask[w] = bal;
        }
        __syncthreads();

        // gather: 2 threads per edge, write (hs,hd) transposed [k][e]
        {
            int e = tid >> 1, r = tid & 1;
            const float4* h1p = (const float4*)(g_hnodes + ((size_t)b * NN + s_ei[2 * e]) * DD);
            const float4* h2p = (const float4*)(g_hnodes + ((size_t)b * NN + s_ei[2 * e + 1]) * DD);
#pragma unroll
            for (int i = 0; i < 8; i++) {
                int q = r * 8 + i;
                float4 a = h1p[q], c = h2p[q];
                int k = q * 4;
                s_h[(k + 0) * SHP + e] = make_float2(a.x + c.x, a.x - c.x);
                s_h[(k + 1) * SHP + e] = make_float2(a.y + c.y, a.y - c.y);
                s_h[(k + 2) * SHP + e] = make_float2(a.z + c.z, a.z - c.z);
                s_h[(k + 3) * SHP + e] = make_float2(a.w + c.w, a.w - c.w);
            }
        }
        if (tid == 0) {
            int c = __popc(s_mask[0]) + __popc(s_mask[1]);
            if (b == 0) cnt0 += c; else cnt1 += c;
        }
        __syncthreads();

        // register-blocked compute: 8 edges x 4 dims per thread, (p,q) packed f32x2
        unsigned long long acc[8][4];
#pragma unroll
        for (int e = 0; e < 8; e++)
#pragma unroll
            for (int j = 0; j < 4; j++) acc[e][j] = 0ull;

#pragma unroll 4
        for (int k = 0; k < 64; k++) {
            const ulonglong2* hp = (const ulonglong2*)(s_h + k * SHP + e0);
            ulonglong2 ha = hp[0], hb = hp[1], hc = hp[2], hd_ = hp[3];
            const ulonglong2* wp = (const ulonglong2*)(s_w + k * 64 + d0);
            ulonglong2 wa = wp[0], wb = wp[1];
            unsigned long long hv[8] = {ha.x, ha.y, hb.x, hb.y, hc.x, hc.y, hd_.x, hd_.y};
#pragma unroll
            for (int e = 0; e < 8; e++) {
                FMA2(acc[e][0], hv[e], wa.x);
                FMA2(acc[e][1], hv[e], wa.y);
                FMA2(acc[e][2], hv[e], wb.x);
                FMA2(acc[e][3], hv[e], wb.y);
            }
        }

        // epilogue
        const unsigned mword = s_mask[e0 >> 5];
        float bias[4];
#pragma unroll
        for (int j = 0; j < 4; j++) bias[j] = s_be[d0 + j];
        float msum[4] = {0.f, 0.f, 0.f, 0.f};

#pragma unroll
        for (int e = 0; e < 8; e++) {
            bool m = (mword >> ((e0 + e) & 31)) & 1u;
            float4 o;
            float ov[4];
#pragma unroll
            for (int j = 0; j < 4; j++) {
                float p = __uint_as_float((unsigned)(acc[e][j] & 0xffffffffu));
                float q = __uint_as_float((unsigned)(acc[e][j] >> 32));
                float s = fmaf(0.5f, p + q, bias[j]);
                float t = fmaf(0.5f, p - q, bias[j]);
                float v = 0.5f * (ftanh(s) + ftanh(t));
                ov[j] = m ? v : 0.0f;
                msum[j] += ov[j];
            }
            o.x = ov[0]; o.y = ov[1]; o.z = ov[2]; o.w = ov[3];
            *(float4*)(out_policy + (size_t)(eg + e0 + e) * DD + d0) = o;
        }

        // reduce mean partials across the 8 edge-groups (lane bits 0..2)
#pragma unroll
        for (int j = 0; j < 4; j++) {
            float v = msum[j];
            v += __shfl_xor_sync(0xffffffffu, v, 1);
            v += __shfl_xor_sync(0xffffffffu, v, 2);
            v += __shfl_xor_sync(0xffffffffu, v, 4);
            if (el == 0) s_sum[b * DD + d0 + j] += v;
        }
    }

    __syncthreads();
    if (tid < BB * DD) atomicAdd(&g_sum[tid], s_sum[tid]);
    if (tid == 0) {
        if (cnt0) atomicAdd(&g_cnt[0], cnt0);
        if (cnt1) atomicAdd(&g_cnt[1], cnt1);
    }
}

// -------- finalize --------
__global__ void k_final(const float* __restrict__ numerical,
                        const float* __restrict__ stage,
                        const float* __restrict__ W1, const float* __restrict__ b1,
                        const float* __restrict__ W2, const float* __restrict__ b2,
                        float* __restrict__ out_value)
{
    __shared__ float t1[BB * H0];
    int t = threadIdx.x;
    if (t < BB * H0) {
        int b = t / H0, j = t % H0;
        float acc = b1[j];
#pragma unroll
        for (int k = 0; k < NODE_DIM; k++) acc = fmaf(numerical[b * NODE_DIM + k], W1[k * H0 + j], acc);
        t1[t] = ftanh(acc);
    }
    __syncthreads();
    if (t < BB * H1) {
        int b = t / H1, j = t % H1;
        float acc = b2[j];
#pragma unroll 8
        for (int k = 0; k < H0; k++) acc = fmaf(t1[b * H0 + k], W2[k * H1 + j], acc);
        out_value[b * 130 + j] = ftanh(acc);
        out_value[b * 130 + 64 + j] = g_sum[b * DD + j] / (float)g_cnt[b];
    }
    if (t < BB * 2) {
        int b = t >> 1, s2 = t & 1;
        out_value[b * 130 + 128 + s2] = stage[b * 2 + s2];
    }
}

// -------- launch --------
extern "C" void kernel_launch(void* const* d_in, const int* in_sizes, int n_in,
                              void* d_out, int out_size) {
    (void)in_sizes; (void)n_in; (void)out_size;
    const float* numerical    = (const float*)d_in[0];
    const float* node_feature = (const float*)d_in[1];
    const int*   edge_index   = (const int*)d_in[2];
    const void*  edge_mask    = d_in[3];
    const float* stage        = (const float*)d_in[4];
    const float* W1 = (const float*)d_in[5];
    const float* b1 = (const float*)d_in[6];
    const float* W2 = (const float*)d_in[7];
    const float* b2 = (const float*)d_in[8];
    const float* Wn = (const float*)d_in[9];
    const float* bn = (const float*)d_in[10];
    const float* We = (const float*)d_in[11];
    const float* be = (const float*)d_in[12];

    float* out        = (float*)d_out;
    float* out_policy = out;
    float* out_value  = out + (size_t)BB * EE * DD;

    cudaFuncSetAttribute(k_edges, cudaFuncAttributeMaxDynamicSharedMemorySize, EDGE_SMEM);

    k_init <<<1, 256>>>((const unsigned int*)edge_mask);
    k_nodes<<<2960, 256>>>(node_feature, Wn, bn);
    k_edges<<<444, 128, EDGE_SMEM>>>(We, be, edge_index, edge_mask, out_policy);
    k_final<<<1, 256>>>(numerical, stage, W1, b1, W2, b2, out_value);
}

// round 3
// speedup vs baseline: 1.7749x; 1.7749x over previous
#include <cuda_runtime.h>
#include <math.h>
#include <stdint.h>

#define BB 2
#define NN 100000
#define EE 400000
#define NODE_DIM 32
#define DD 64
#define H0 128
#define H1 64
#define TILE_E 64
#define SHP 66   // s_h row pitch in f32x2 units

// -------- device scratch --------
__device__ float g_hnodes[(size_t)BB * NN * DD];   // 51.2 MB
__device__ float g_sum[BB * DD];
__device__ int   g_cnt[BB];
__device__ int   g_mask_mode;                      // 0=u8, 1=i32, 2=f32

// fast accurate tanh: MUFU ex2 + rcp, abs err ~1e-7
__device__ __forceinline__ float ftanh(float x) {
    float e = __expf(2.0f * x);
    return 1.0f - __fdividef(2.0f, e + 1.0f);
}

__device__ __forceinline__ bool mask_at(const void* m, long long i, int mode) {
    if (mode == 1) return ((const int*)m)[i] != 0;
    if (mode == 2) return ((const float*)m)[i] != 0.0f;
    return ((const unsigned char*)m)[i] != 0;
}

// -------- init: zero accumulators + detect mask dtype --------
__global__ void k_init(const unsigned int* mask_words) {
    int t = threadIdx.x;
    if (t < BB * DD) g_sum[t] = 0.0f;
    if (t < BB) g_cnt[t] = 0;
    __shared__ int s_notint, s_notfl;
    if (t == 0) { s_notint = 0; s_notfl = 0; }
    __syncthreads();
    int ni = 0, nf = 0;
    for (int i = t; i < 1024; i += blockDim.x) {
        unsigned w = mask_words[i];
        if (w > 1u) ni = 1;
        if (w != 0u && w != 0x3F800000u) nf = 1;
    }
    if (ni) atomicOr(&s_notint, 1);
    if (nf) atomicOr(&s_notfl, 1);
    __syncthreads();
    if (t == 0) g_mask_mode = (!s_notint) ? 1 : ((!s_notfl) ? 2 : 0);
}

// -------- node MLP: h_nodes = tanh(nf @ Wn + bn) --------
__global__ void k_nodes(const float* __restrict__ nf,
                        const float* __restrict__ Wn,
                        const float* __restrict__ bn) {
    __shared__ float2 ws[NODE_DIM][32];
    __shared__ float2 bs[32];
    int tid = threadIdx.x, lane = tid & 31, w = tid >> 5;
    for (int i = tid; i < NODE_DIM * 32; i += blockDim.x) {
        int k = i >> 5, j = i & 31;
        ws[k][j] = make_float2(Wn[k * DD + j], Wn[k * DD + j + 32]);
    }
    if (tid < 32) bs[tid] = make_float2(bn[tid], bn[tid + 32]);
    __syncthreads();

    const int nrows = BB * NN;
    const int warps = (blockDim.x >> 5) * gridDim.x;
    for (int row = blockIdx.x * (blockDim.x >> 5) + w; row < nrows; row += warps) {
        float x = nf[(size_t)row * NODE_DIM + lane];
        float2 acc = bs[lane];
#pragma unroll
        for (int k = 0; k < NODE_DIM; k++) {
            float v = __shfl_sync(0xffffffffu, x, k);
            float2 wv = ws[k][lane];
            acc.x = fmaf(v, wv.x, acc.x);
            acc.y = fmaf(v, wv.y, acc.y);
        }
        float* o = g_hnodes + (size_t)row * DD;
        o[lane]      = ftanh(acc.x);
        o[lane + 32] = ftanh(acc.y);
    }
}

// -------- edge kernel --------
// dynamic smem layout (bytes):
//   [0, 32768)       float2 s_w[64][64]      (wsum, wdiff)[k][d]
//   [32768, 66560)   float2 s_h[64][SHP=66]  (hs, hd)[k][e]
//   [66560, 66816)   float  s_be[64]
//   [66816, 67328)   float  s_sum[128]
//   [67328, 67840)   int    s_ei[128]
//   [67840, 67848)   unsigned s_mask[2]
#define EDGE_SMEM 67968

#define FMA2(acc, a, b) asm("fma.rn.f32x2 %0, %1, %2, %0;" : "+l"(acc) : "l"(a), "l"(b))

__global__ void __launch_bounds__(128, 3) k_edges(
    const float* __restrict__ We, const float* __restrict__ be,
    const int* __restrict__ eidx, const void* __restrict__ mask,
    float* __restrict__ out_policy)
{
    extern __shared__ unsigned char dsm[];
    float2*   s_w    = (float2*)dsm;
    float2*   s_h    = (float2*)(dsm + 32768);
    float*    s_be   = (float*)(dsm + 66560);
    float*    s_sum  = (float*)(dsm + 66816);
    int*      s_ei   = (int*)(dsm + 67328);
    unsigned* s_mask = (unsigned*)(dsm + 67840);

    const int tid = threadIdx.x;
    const int lane = tid & 31, w = tid >> 5;
    const int mode = g_mask_mode;

    // (Wa+Wb, Wa-Wb) into smem once per persistent block
    for (int i = tid; i < 64 * 64; i += 128) {
        int k = i >> 6, d = i & 63;
        float a = We[k * 64 + d];
        float b = We[(64 + k) * 64 + d];
        s_w[i] = make_float2(a + b, a - b);
    }
    if (tid < 64) s_be[tid] = be[tid];
    if (tid < BB * DD) s_sum[tid] = 0.0f;

    const int d0 = w * 16;                // warp owns 16 dims

    int cnt0 = 0, cnt1 = 0;

    const int tiles_per_b = EE / TILE_E;  // 6250
    const int ntiles = BB * tiles_per_b;  // 12500

    for (int tile = blockIdx.x; tile < ntiles; tile += gridDim.x) {
        const int b = tile / tiles_per_b;
        const long long eg = (long long)b * EE + (long long)(tile - b * tiles_per_b) * TILE_E;

        __syncthreads();   // protect s_ei/s_mask/s_h from previous tile readers
        s_ei[tid] = eidx[eg * 2 + tid];
        if (w < 2) {
            bool m = mask_at(mask, eg + w * 32 + lane, mode);
            unsigned bal = __ballot_sync(0xffffffffu, m);
            if (lane == 0) s_mask[w] = bal;
        }
        __syncthreads();

        // gather: 2 threads per edge; q = r + 2*i interleave keeps paired
        // threads' STS addresses 8 banks apart (no store conflicts)
        {
            int e = tid >> 1, r = tid & 1;
            const float4* h1p = (const float4*)(g_hnodes + ((size_t)b * NN + s_ei[2 * e]) * DD);
            const float4* h2p = (const float4*)(g_hnodes + ((size_t)b * NN + s_ei[2 * e + 1]) * DD);
#pragma unroll
            for (int i = 0; i < 8; i++) {
                int q = r + 2 * i;
                float4 a = h1p[q], c = h2p[q];
                int k = q * 4;
                s_h[(k + 0) * SHP + e] = make_float2(a.x + c.x, a.x - c.x);
                s_h[(k + 1) * SHP + e] = make_float2(a.y + c.y, a.y - c.y);
                s_h[(k + 2) * SHP + e] = make_float2(a.z + c.z, a.z - c.z);
                s_h[(k + 3) * SHP + e] = make_float2(a.w + c.w, a.w - c.w);
            }
        }
        if (tid == 0) {
            int c = __popc(s_mask[0]) + __popc(s_mask[1]);
            if (b == 0) cnt0 += c; else cnt1 += c;
        }
        __syncthreads();

        // compute: warp w owns dims [16w,16w+16); each lane owns edges lane, lane+32
        unsigned long long acc0[16], acc1[16];
#pragma unroll
        for (int j = 0; j < 16; j++) { acc0[j] = 0ull; acc1[j] = 0ull; }

#pragma unroll 2
        for (int k = 0; k < 64; k++) {
            unsigned long long h0 = *(const unsigned long long*)&s_h[k * SHP + lane];
            unsigned long long h1 = *(const unsigned long long*)&s_h[k * SHP + 32 + lane];
            const ulonglong2* wp = (const ulonglong2*)&s_w[k * 64 + d0];
#pragma unroll
            for (int j2 = 0; j2 < 8; j2++) {
                ulonglong2 ww = wp[j2];
                FMA2(acc0[2 * j2],     h0, ww.x);
                FMA2(acc0[2 * j2 + 1], h0, ww.y);
                FMA2(acc1[2 * j2],     h1, ww.x);
                FMA2(acc1[2 * j2 + 1], h1, ww.y);
            }
        }

        // epilogue for both edges
        const bool m0 = (s_mask[0] >> lane) & 1u;
        const bool m1 = (s_mask[1] >> lane) & 1u;
        float msum[16];
#pragma unroll
        for (int j = 0; j < 16; j++) msum[j] = 0.0f;

        float4* op0 = (float4*)(out_policy + (size_t)(eg + lane) * DD + d0);
        float4* op1 = (float4*)(out_policy + (size_t)(eg + 32 + lane) * DD + d0);

#pragma unroll
        for (int half = 0; half < 2; half++) {
            const unsigned long long* acc = half ? acc1 : acc0;
            const bool msk = half ? m1 : m0;
            float hv[16];
#pragma unroll
            for (int j = 0; j < 16; j++) {
                float p = __uint_as_float((unsigned)(acc[j] & 0xffffffffu));
                float q = __uint_as_float((unsigned)(acc[j] >> 32));
                float bias = s_be[d0 + j];
                float s = fmaf(0.5f, p + q, bias);
                float t = fmaf(0.5f, p - q, bias);
                float v = 0.5f * (ftanh(s) + ftanh(t));
                hv[j] = msk ? v : 0.0f;
                msum[j] += hv[j];
            }
            float4* op = half ? op1 : op0;
            op[0] = make_float4(hv[0],  hv[1],  hv[2],  hv[3]);
            op[1] = make_float4(hv[4],  hv[5],  hv[6],  hv[7]);
            op[2] = make_float4(hv[8],  hv[9],  hv[10], hv[11]);
            op[3] = make_float4(hv[12], hv[13], hv[14], hv[15]);
        }

        // mean partials: reduce over 32 lanes (all distinct edges)
#pragma unroll
        for (int j = 0; j < 16; j++) {
            float v = msum[j];
            v += __shfl_xor_sync(0xffffffffu, v, 16);
            v += __shfl_xor_sync(0xffffffffu, v, 8);
            v += __shfl_xor_sync(0xffffffffu, v, 4);
            v += __shfl_xor_sync(0xffffffffu, v, 2);
            v += __shfl_xor_sync(0xffffffffu, v, 1);
            if (lane == 0) s_sum[b * DD + d0 + j] += v;
        }
    }

    __syncthreads();
    if (tid < BB * DD) atomicAdd(&g_sum[tid], s_sum[tid]);
    if (tid == 0) {
        if (cnt0) atomicAdd(&g_cnt[0], cnt0);
        if (cnt1) atomicAdd(&g_cnt[1], cnt1);
    }
}

// -------- finalize --------
__global__ void k_final(const float* __restrict__ numerical,
                        const float* __restrict__ stage,
                        const float* __restrict__ W1, const float* __restrict__ b1,
                        const float* __restrict__ W2, const float* __restrict__ b2,
                        float* __restrict__ out_value)
{
    __shared__ float t1[BB * H0];
    int t = threadIdx.x;
    if (t < BB * H0) {
        int b = t / H0, j = t % H0;
        float acc = b1[j];
#pragma unroll
        for (int k = 0; k < NODE_DIM; k++) acc = fmaf(numerical[b * NODE_DIM + k], W1[k * H0 + j], acc);
        t1[t] = ftanh(acc);
    }
    __syncthreads();
    if (t < BB * H1) {
        int b = t / H1, j = t % H1;
        float acc = b2[j];
#pragma unroll 8
        for (int k = 0; k < H0; k++) acc = fmaf(t1[b * H0 + k], W2[k * H1 + j], acc);
        out_value[b * 130 + j] = ftanh(acc);
        out_value[b * 130 + 64 + j] = g_sum[b * DD + j] / (float)g_cnt[b];
    }
    if (t < BB * 2) {
        int b = t >> 1, s2 = t & 1;
        out_value[b * 130 + 128 + s2] = stage[b * 2 + s2];
    }
}

// -------- launch --------
extern "C" void kernel_launch(void* const* d_in, const int* in_sizes, int n_in,
                              void* d_out, int out_size) {
    (void)in_sizes; (void)n_in; (void)out_size;
    const float* numerical    = (const float*)d_in[0];
    const float* node_feature = (const float*)d_in[1];
    const int*   edge_index   = (const int*)d_in[2];
    const void*  edge_mask    = d_in[3];
    const float* stage        = (const float*)d_in[4];
    const float* W1 = (const float*)d_in[5];
    const float* b1 = (const float*)d_in[6];
    const float* W2 = (const float*)d_in[7];
    const float* b2 = (const float*)d_in[8];
    const float* Wn = (const float*)d_in[9];
    const float* bn = (const float*)d_in[10];
    const float* We = (const float*)d_in[11];
    const float* be = (const float*)d_in[12];

    float* out        = (float*)d_out;
    float* out_policy = out;
    float* out_value  = out + (size_t)BB * EE * DD;

    cudaFuncSetAttribute(k_edges, cudaFuncAttributeMaxDynamicSharedMemorySize, EDGE_SMEM);

    k_init <<<1, 256>>>((const unsigned int*)edge_mask);
    k_nodes<<<2960, 256>>>(node_feature, Wn, bn);
    k_edges<<<444, 128, EDGE_SMEM>>>(We, be, edge_index, edge_mask, out_policy);
    k_final<<<1, 256>>>(numerical, stage, W1, b1, W2, b2, out_value);
}

// round 4
// speedup vs baseline: 2.6106x; 1.4708x over previous
#include <cuda_runtime.h>
#include <math.h>
#include <stdint.h>

#define BB 2
#define NN 100000
#define EE 400000
#define NODE_DIM 32
#define DD 64
#define H0 128
#define H1 64
#define TILE_E 64
#define SHP 66          // s_h row pitch in f32x2 units
#define W_PER_B 500     // scan warps per batch
#define SPAN 800        // edges per scan warp (25 chunks of 32)

// -------- device scratch --------
__device__ float g_hnodes[(size_t)BB * NN * DD];   // 51.2 MB
__device__ int   g_active[(size_t)BB * EE];        // compacted active edge ids
__device__ int   g_wcnt[BB * W_PER_B];
__device__ int   g_wbase[BB * W_PER_B];
__device__ float g_sum[BB * DD];
__device__ int   g_cnt[BB];
__device__ int   g_mask_mode;                      // 0=u8, 1=i32, 2=f32

// fast accurate tanh: MUFU ex2 + rcp, abs err ~1e-7
__device__ __forceinline__ float ftanh(float x) {
    float e = __expf(2.0f * x);
    return 1.0f - __fdividef(2.0f, e + 1.0f);
}

__device__ __forceinline__ bool mask_at(const void* m, long long i, int mode) {
    if (mode == 1) return ((const int*)m)[i] != 0;
    if (mode == 2) return ((const float*)m)[i] != 0.0f;
    return ((const unsigned char*)m)[i] != 0;
}

// -------- init: zero g_sum + detect mask dtype --------
__global__ void k_init(const unsigned int* mask_words) {
    int t = threadIdx.x;
    if (t < BB * DD) g_sum[t] = 0.0f;
    __shared__ int s_notint, s_notfl;
    if (t == 0) { s_notint = 0; s_notfl = 0; }
    __syncthreads();
    int ni = 0, nf = 0;
    for (int i = t; i < 1024; i += blockDim.x) {
        unsigned w = mask_words[i];
        if (w > 1u) ni = 1;
        if (w != 0u && w != 0x3F800000u) nf = 1;
    }
    if (ni) atomicOr(&s_notint, 1);
    if (nf) atomicOr(&s_notfl, 1);
    __syncthreads();
    if (t == 0) g_mask_mode = (!s_notint) ? 1 : ((!s_notfl) ? 2 : 0);
}

// -------- compaction pass A: per-warp active counts --------
__global__ void k_cntA(const void* __restrict__ mask) {
    const int mode = g_mask_mode;
    int wg = blockIdx.x * 4 + (threadIdx.x >> 5);       // 0..999
    int lane = threadIdx.x & 31;
    int b = wg / W_PER_B;
    long long base = (long long)b * EE + (long long)(wg % W_PER_B) * SPAN;
    int cnt = 0;
#pragma unroll 5
    for (int c = 0; c < SPAN / 32; c++) {
        bool m = mask_at(mask, base + c * 32 + lane, mode);
        unsigned bal = __ballot_sync(0xffffffffu, m);
        cnt += __popc(bal);
    }
    if (lane == 0) g_wcnt[wg] = cnt;
}

// -------- compaction pass B: segmented exclusive scan (1 block) --------
__global__ void k_scanB() {
    __shared__ int s[1024];
    int t = threadIdx.x;                     // 1024 threads: 512 per batch region
    int tl = t & 511;                        // local within region
    int b = t >> 9;
    int v = (tl < W_PER_B) ? g_wcnt[b * W_PER_B + tl] : 0;
    s[t] = v;
    __syncthreads();
#pragma unroll
    for (int off = 1; off < 512; off <<= 1) {
        int add = (tl >= off) ? s[t - off] : 0;
        __syncthreads();
        s[t] += add;
        __syncthreads();
    }
    if (tl < W_PER_B) g_wbase[b * W_PER_B + tl] = s[t] - v;   // exclusive
    if (tl == W_PER_B - 1) g_cnt[b] = s[t];                   // total actives
}

// -------- compaction pass C: scatter actives + zero inactive out rows --------
__global__ void k_scatC(const void* __restrict__ mask, float* __restrict__ out_policy) {
    const int mode = g_mask_mode;
    int wg = blockIdx.x * 4 + (threadIdx.x >> 5);
    int lane = threadIdx.x & 31;
    int b = wg / W_PER_B;
    long long ebase = (long long)(wg % W_PER_B) * SPAN;       // within batch
    long long gbase = (long long)b * EE + ebase;
    int running = g_wbase[wg];
    const float4 z = make_float4(0.f, 0.f, 0.f, 0.f);
#pragma unroll 1
    for (int c = 0; c < SPAN / 32; c++) {
        long long i = gbase + c * 32 + lane;                  // global edge slot
        int il = (int)(ebase + c * 32 + lane);                // edge id within batch
        bool m = mask_at(mask, i, mode);
        unsigned bal = __ballot_sync(0xffffffffu, m);
        int rank = __popc(bal & ((1u << lane) - 1u));
        if (m) {
            g_active[(size_t)b * EE + running + rank] = il;
        } else {
            float4* row = (float4*)(out_policy + (size_t)i * DD);
#pragma unroll
            for (int q = 0; q < 16; q++) row[q] = z;
        }
        running += __popc(bal);
    }
}

// -------- node MLP: h_nodes = tanh(nf @ Wn + bn) --------
__global__ void k_nodes(const float* __restrict__ nf,
                        const float* __restrict__ Wn,
                        const float* __restrict__ bn) {
    __shared__ float2 ws[NODE_DIM][32];
    __shared__ float2 bs[32];
    int tid = threadIdx.x, lane = tid & 31, w = tid >> 5;
    for (int i = tid; i < NODE_DIM * 32; i += blockDim.x) {
        int k = i >> 5, j = i & 31;
        ws[k][j] = make_float2(Wn[k * DD + j], Wn[k * DD + j + 32]);
    }
    if (tid < 32) bs[tid] = make_float2(bn[tid], bn[tid + 32]);
    __syncthreads();

    const int nrows = BB * NN;
    const int warps = (blockDim.x >> 5) * gridDim.x;
    for (int row = blockIdx.x * (blockDim.x >> 5) + w; row < nrows; row += warps) {
        float x = nf[(size_t)row * NODE_DIM + lane];
        float2 acc = bs[lane];
#pragma unroll
        for (int k = 0; k < NODE_DIM; k++) {
            float v = __shfl_sync(0xffffffffu, x, k);
            float2 wv = ws[k][lane];
            acc.x = fmaf(v, wv.x, acc.x);
            acc.y = fmaf(v, wv.y, acc.y);
        }
        float* o = g_hnodes + (size_t)row * DD;
        o[lane]      = ftanh(acc.x);
        o[lane + 32] = ftanh(acc.y);
    }
}

// -------- edge kernel (active edges only) --------
// dynamic smem layout (bytes):
//   [0, 32768)       float2 s_w[64][64]      (wsum, wdiff)[k][d]
//   [32768, 66560)   float2 s_h[64][SHP=66]  (hs, hd)[k][e]
//   [66560, 66816)   float  s_be[64]
//   [66816, 67328)   float  s_sum[128]
//   [67328, 67840)   int    s_ei[128]
//   [67840, 68096)   int    s_ae[64]
#define EDGE_SMEM 68096

#define FMA2(acc, a, b) asm("fma.rn.f32x2 %0, %1, %2, %0;" : "+l"(acc) : "l"(a), "l"(b))

__global__ void __launch_bounds__(128, 3) k_edges(
    const float* __restrict__ We, const float* __restrict__ be,
    const int* __restrict__ eidx,
    float* __restrict__ out_policy)
{
    extern __shared__ unsigned char dsm[];
    float2* s_w   = (float2*)dsm;
    float2* s_h   = (float2*)(dsm + 32768);
    float*  s_be  = (float*)(dsm + 66560);
    float*  s_sum = (float*)(dsm + 66816);
    int*    s_ei  = (int*)(dsm + 67328);
    int*    s_ae  = (int*)(dsm + 67840);

    const int tid = threadIdx.x;
    const int lane = tid & 31, w = tid >> 5;

    // (Wa+Wb, Wa-Wb) into smem once per persistent block
    for (int i = tid; i < 64 * 64; i += 128) {
        int k = i >> 6, d = i & 63;
        float a = We[k * 64 + d];
        float b = We[(64 + k) * 64 + d];
        s_w[i] = make_float2(a + b, a - b);
    }
    if (tid < 64) s_be[tid] = be[tid];
    if (tid < BB * DD) s_sum[tid] = 0.0f;

    const int d0 = w * 16;                // warp owns 16 dims
    const int cntb[2] = { g_cnt[0], g_cnt[1] };

    const int tiles_per_b = EE / TILE_E;  // 6250 (worst case)
    const int ntiles = BB * tiles_per_b;

    for (int tile = blockIdx.x; tile < ntiles; tile += gridDim.x) {
        const int b = tile / tiles_per_b;
        const int cnt = cntb[b];
        const int t0 = (tile - b * tiles_per_b) * TILE_E;
        if (t0 >= cnt) continue;
        const int nval = min(TILE_E, cnt - t0);
        const unsigned v0 = (nval >= 32) ? 0xffffffffu : ((1u << nval) - 1u);
        const unsigned v1 = (nval >= 64) ? 0xffffffffu
                          : ((nval > 32) ? ((1u << (nval - 32)) - 1u) : 0u);

        __syncthreads();   // protect s_ei/s_ae/s_h from previous tile readers
        if (tid < TILE_E) {
            int slot = t0 + tid;
            int ae = (slot < cnt) ? g_active[(size_t)b * EE + slot] : 0;
            s_ae[tid] = ae;
            int2 pr = ((const int2*)eidx)[(size_t)b * EE + ae];
            s_ei[2 * tid] = pr.x;
            s_ei[2 * tid + 1] = pr.y;
        }
        __syncthreads();

        // gather: 2 threads per edge; interleaved q keeps STS conflict-free
        {
            int e = tid >> 1, r = tid & 1;
            const float4* h1p = (const float4*)(g_hnodes + ((size_t)b * NN + s_ei[2 * e]) * DD);
            const float4* h2p = (const float4*)(g_hnodes + ((size_t)b * NN + s_ei[2 * e + 1]) * DD);
#pragma unroll
            for (int i = 0; i < 8; i++) {
                int q = r + 2 * i;
                float4 a = h1p[q], c = h2p[q];
                int k = q * 4;
                s_h[(k + 0) * SHP + e] = make_float2(a.x + c.x, a.x - c.x);
                s_h[(k + 1) * SHP + e] = make_float2(a.y + c.y, a.y - c.y);
                s_h[(k + 2) * SHP + e] = make_float2(a.z + c.z, a.z - c.z);
                s_h[(k + 3) * SHP + e] = make_float2(a.w + c.w, a.w - c.w);
            }
        }
        __syncthreads();

        // compute: warp w owns dims [16w,16w+16); lane owns edges lane, lane+32
        unsigned long long acc0[16], acc1[16];
#pragma unroll
        for (int j = 0; j < 16; j++) { acc0[j] = 0ull; acc1[j] = 0ull; }

#pragma unroll 2
        for (int k = 0; k < 64; k++) {
            unsigned long long h0 = *(const unsigned long long*)&s_h[k * SHP + lane];
            unsigned long long h1 = *(const unsigned long long*)&s_h[k * SHP + 32 + lane];
            const ulonglong2* wp = (const ulonglong2*)&s_w[k * 64 + d0];
#pragma unroll
            for (int j2 = 0; j2 < 8; j2++) {
                ulonglong2 ww = wp[j2];
                FMA2(acc0[2 * j2],     h0, ww.x);
                FMA2(acc0[2 * j2 + 1], h0, ww.y);
                FMA2(acc1[2 * j2],     h1, ww.x);
                FMA2(acc1[2 * j2 + 1], h1, ww.y);
            }
        }

        // epilogue for both edges
        const bool ok0 = (v0 >> lane) & 1u;
        const bool ok1 = (v1 >> lane) & 1u;
        float msum[16];
#pragma unroll
        for (int j = 0; j < 16; j++) msum[j] = 0.0f;

#pragma unroll
        for (int half = 0; half < 2; half++) {
            const unsigned long long* acc = half ? acc1 : acc0;
            const bool msk = half ? ok1 : ok0;
            float hv[16];
#pragma unroll
            for (int j = 0; j < 16; j++) {
                float p = __uint_as_float((unsigned)(acc[j] & 0xffffffffu));
                float q = __uint_as_float((unsigned)(acc[j] >> 32));
                float bias = s_be[d0 + j];
                float s = fmaf(0.5f, p + q, bias);
                float t = fmaf(0.5f, p - q, bias);
                float v = 0.5f * (ftanh(s) + ftanh(t));
                hv[j] = msk ? v : 0.0f;
                msum[j] += hv[j];
            }
            if (msk) {
                int ae = s_ae[half * 32 + lane];
                float4* op = (float4*)(out_policy + ((size_t)b * EE + ae) * DD + d0);
                op[0] = make_float4(hv[0],  hv[1],  hv[2],  hv[3]);
                op[1] = make_float4(hv[4],  hv[5],  hv[6],  hv[7]);
                op[2] = make_float4(hv[8],  hv[9],  hv[10], hv[11]);
                op[3] = make_float4(hv[12], hv[13], hv[14], hv[15]);
            }
        }

        // mean partials: reduce over 32 lanes
#pragma unroll
        for (int j = 0; j < 16; j++) {
            float v = msum[j];
            v += __shfl_xor_sync(0xffffffffu, v, 16);
            v += __shfl_xor_sync(0xffffffffu, v, 8);
            v += __shfl_xor_sync(0xffffffffu, v, 4);
            v += __shfl_xor_sync(0xffffffffu, v, 2);
            v += __shfl_xor_sync(0xffffffffu, v, 1);
            if (lane == 0) s_sum[b * DD + d0 + j] += v;
        }
    }

    __syncthreads();
    if (tid < BB * DD) atomicAdd(&g_sum[tid], s_sum[tid]);
}

// -------- finalize --------
__global__ void k_final(const float* __restrict__ numerical,
                        const float* __restrict__ stage,
                        const float* __restrict__ W1, const float* __restrict__ b1,
                        const float* __restrict__ W2, const float* __restrict__ b2,
                        float* __restrict__ out_value)
{
    __shared__ float t1[BB * H0];
    int t = threadIdx.x;
    if (t < BB * H0) {
        int b = t / H0, j = t % H0;
        float acc = b1[j];
#pragma unroll
        for (int k = 0; k < NODE_DIM; k++) acc = fmaf(numerical[b * NODE_DIM + k], W1[k * H0 + j], acc);
        t1[t] = ftanh(acc);
    }
    __syncthreads();
    if (t < BB * H1) {
        int b = t / H1, j = t % H1;
        float acc = b2[j];
#pragma unroll 8
        for (int k = 0; k < H0; k++) acc = fmaf(t1[b * H0 + k], W2[k * H1 + j], acc);
        out_value[b * 130 + j] = ftanh(acc);
        out_value[b * 130 + 64 + j] = g_sum[b * DD + j] / (float)g_cnt[b];
    }
    if (t < BB * 2) {
        int b = t >> 1, s2 = t & 1;
        out_value[b * 130 + 128 + s2] = stage[b * 2 + s2];
    }
}

// -------- launch --------
extern "C" void kernel_launch(void* const* d_in, const int* in_sizes, int n_in,
                              void* d_out, int out_size) {
    (void)in_sizes; (void)n_in; (void)out_size;
    const float* numerical    = (const float*)d_in[0];
    const float* node_feature = (const float*)d_in[1];
    const int*   edge_index   = (const int*)d_in[2];
    const void*  edge_mask    = d_in[3];
    const float* stage        = (const float*)d_in[4];
    const float* W1 = (const float*)d_in[5];
    const float* b1 = (const float*)d_in[6];
    const float* W2 = (const float*)d_in[7];
    const float* b2 = (const float*)d_in[8];
    const float* Wn = (const float*)d_in[9];
    const float* bn = (const float*)d_in[10];
    const float* We = (const float*)d_in[11];
    const float* be = (const float*)d_in[12];

    float* out        = (float*)d_out;
    float* out_policy = out;
    float* out_value  = out + (size_t)BB * EE * DD;

    cudaFuncSetAttribute(k_edges, cudaFuncAttributeMaxDynamicSharedMemorySize, EDGE_SMEM);

    k_init <<<1, 256>>>((const unsigned int*)edge_mask);
    k_cntA <<<250, 128>>>(edge_mask);
    k_scanB<<<1, 1024>>>();
    k_scatC<<<250, 128>>>(edge_mask, out_policy);
    k_nodes<<<2960, 256>>>(node_feature, Wn, bn);
    k_edges<<<444, 128, EDGE_SMEM>>>(We, be, edge_index, out_policy);
    k_final<<<1, 256>>>(numerical, stage, W1, b1, W2, b2, out_value);
}

// round 5
// speedup vs baseline: 2.8622x; 1.0964x over previous
#include <cuda_runtime.h>
#include <math.h>
#include <stdint.h>

#define BB 2
#define NN 100000
#define EE 400000
#define NODE_DIM 32
#define DD 64
#define H0 128
#define H1 64
#define TILE_E 64
#define SHP 66          // s_h row pitch in f32x2 units
#define W_PER_B 500     // scan warps per batch
#define SPAN 800        // edges per scan warp

// -------- device scratch --------
__device__ float g_hnodes[(size_t)BB * NN * DD];   // 51.2 MB
__device__ int   g_active[(size_t)BB * EE];
__device__ int   g_wcnt[BB * W_PER_B];
__device__ int   g_wbase[BB * W_PER_B];
__device__ float g_sum[BB * DD];
__device__ int   g_cnt[BB];
__device__ int   g_mask_mode;                      // 0=u8, 1=i32, 2=f32

__device__ __forceinline__ float ftanh(float x) {
    float e = __expf(2.0f * x);
    return 1.0f - __fdividef(2.0f, e + 1.0f);
}

__device__ __forceinline__ bool mask_at(const void* m, long long i, int mode) {
    if (mode == 1) return ((const int*)m)[i] != 0;
    if (mode == 2) return ((const float*)m)[i] != 0.0f;
    return ((const unsigned char*)m)[i] != 0;
}

// -------- init: zero g_sum + detect mask dtype --------
__global__ void k_init(const unsigned int* mask_words) {
    int t = threadIdx.x;
    if (t < BB * DD) g_sum[t] = 0.0f;
    __shared__ int s_notint, s_notfl;
    if (t == 0) { s_notint = 0; s_notfl = 0; }
    __syncthreads();
    int ni = 0, nf = 0;
    for (int i = t; i < 1024; i += blockDim.x) {
        unsigned w = mask_words[i];
        if (w > 1u) ni = 1;
        if (w != 0u && w != 0x3F800000u) nf = 1;
    }
    if (ni) atomicOr(&s_notint, 1);
    if (nf) atomicOr(&s_notfl, 1);
    __syncthreads();
    if (t == 0) g_mask_mode = (!s_notint) ? 1 : ((!s_notfl) ? 2 : 0);
}

// -------- compaction A: per-warp active counts --------
__global__ void k_cntA(const void* __restrict__ mask) {
    const int mode = g_mask_mode;
    int wg = blockIdx.x * 4 + (threadIdx.x >> 5);
    int lane = threadIdx.x & 31;
    int b = wg / W_PER_B;
    long long base = (long long)b * EE + (long long)(wg % W_PER_B) * SPAN;
    int cnt = 0;
#pragma unroll 5
    for (int c = 0; c < SPAN / 32; c++) {
        bool m = mask_at(mask, base + c * 32 + lane, mode);
        unsigned bal = __ballot_sync(0xffffffffu, m);
        cnt += __popc(bal);
    }
    if (lane == 0) g_wcnt[wg] = cnt;
}

// -------- compaction B: segmented exclusive scan --------
__global__ void k_scanB() {
    __shared__ int s[1024];
    int t = threadIdx.x;
    int tl = t & 511;
    int b = t >> 9;
    int v = (tl < W_PER_B) ? g_wcnt[b * W_PER_B + tl] : 0;
    s[t] = v;
    __syncthreads();
#pragma unroll
    for (int off = 1; off < 512; off <<= 1) {
        int add = (tl >= off) ? s[t - off] : 0;
        __syncthreads();
        s[t] += add;
        __syncthreads();
    }
    if (tl < W_PER_B) g_wbase[b * W_PER_B + tl] = s[t] - v;
    if (tl == W_PER_B - 1) g_cnt[b] = s[t];
}

// -------- compaction C: scatter active edge ids (no zero-fill) --------
__global__ void k_scatC(const void* __restrict__ mask) {
    const int mode = g_mask_mode;
    int wg = blockIdx.x * 4 + (threadIdx.x >> 5);
    int lane = threadIdx.x & 31;
    int b = wg / W_PER_B;
    long long ebase = (long long)(wg % W_PER_B) * SPAN;
    long long gbase = (long long)b * EE + ebase;
    int running = g_wbase[wg];
#pragma unroll 5
    for (int c = 0; c < SPAN / 32; c++) {
        long long i = gbase + c * 32 + lane;
        int il = (int)(ebase + c * 32 + lane);
        bool m = mask_at(mask, i, mode);
        unsigned bal = __ballot_sync(0xffffffffu, m);
        int rank = __popc(bal & ((1u << lane) - 1u));
        if (m) g_active[(size_t)b * EE + running + rank] = il;
        running += __popc(bal);
    }
}

// -------- zero inactive output rows (full-chip, coalesced) --------
__global__ void k_zero(const void* __restrict__ mask, float* __restrict__ out_policy) {
    const int mode = g_mask_mode;
    const float4 z = make_float4(0.f, 0.f, 0.f, 0.f);
    long long stride = (long long)gridDim.x * blockDim.x;
    for (long long i = (long long)blockIdx.x * blockDim.x + threadIdx.x;
         i < (long long)BB * EE * 16; i += stride) {
        long long e = i >> 4;
        if (!mask_at(mask, e, mode)) ((float4*)out_policy)[i] = z;
    }
}

// -------- node MLP --------
__global__ void k_nodes(const float* __restrict__ nf,
                        const float* __restrict__ Wn,
                        const float* __restrict__ bn) {
    __shared__ float2 ws[NODE_DIM][32];
    __shared__ float2 bs[32];
    int tid = threadIdx.x, lane = tid & 31, w = tid >> 5;
    for (int i = tid; i < NODE_DIM * 32; i += blockDim.x) {
        int k = i >> 5, j = i & 31;
        ws[k][j] = make_float2(Wn[k * DD + j], Wn[k * DD + j + 32]);
    }
    if (tid < 32) bs[tid] = make_float2(bn[tid], bn[tid + 32]);
    __syncthreads();

    const int nrows = BB * NN;
    const int warps = (blockDim.x >> 5) * gridDim.x;
    for (int row = blockIdx.x * (blockDim.x >> 5) + w; row < nrows; row += warps) {
        float x = nf[(size_t)row * NODE_DIM + lane];
        float2 acc = bs[lane];
#pragma unroll
        for (int k = 0; k < NODE_DIM; k++) {
            float v = __shfl_sync(0xffffffffu, x, k);
            float2 wv = ws[k][lane];
            acc.x = fmaf(v, wv.x, acc.x);
            acc.y = fmaf(v, wv.y, acc.y);
        }
        float* o = g_hnodes + (size_t)row * DD;
        o[lane]      = ftanh(acc.x);
        o[lane + 32] = ftanh(acc.y);
    }
}

// -------- edge kernel: double-buffered software pipeline --------
// dynamic smem layout (bytes):
//   [0, 32768)         float2 s_w[64][64]
//   [32768, 100352)    float2 s_h[2][64][SHP]   (33792 each)
//   [100352, 100608)   float  s_be[64]
//   [100608, 101120)   float  s_sum[128]
//   [101120, 101632)   int    s_ae[2][64]
#define EDGE_SMEM 101632
#define HBUF (64 * SHP)   // f32x2 per buffer

#define FMA2(acc, a, b) asm("fma.rn.f32x2 %0, %1, %2, %0;" : "+l"(acc) : "l"(a), "l"(b))

__global__ void __launch_bounds__(128, 2) k_edges(
    const float* __restrict__ We, const float* __restrict__ be,
    const int* __restrict__ eidx,
    float* __restrict__ out_policy)
{
    extern __shared__ unsigned char dsm[];
    float2* s_w   = (float2*)dsm;
    float2* s_h   = (float2*)(dsm + 32768);
    float*  s_be  = (float*)(dsm + 100352);
    float*  s_sum = (float*)(dsm + 100608);
    int*    s_ae  = (int*)(dsm + 101120);

    const int tid = threadIdx.x;
    const int lane = tid & 31, w = tid >> 5;

    for (int i = tid; i < 64 * 64; i += 128) {
        int k = i >> 6, d = i & 63;
        float a = We[k * 64 + d];
        float b = We[(64 + k) * 64 + d];
        s_w[i] = make_float2(a + b, a - b);
    }
    if (tid < 64) s_be[tid] = be[tid];
    if (tid < BB * DD) s_sum[tid] = 0.0f;

    const int d0 = w * 16;
    const int cnt0 = g_cnt[0], cnt1 = g_cnt[1];
    const int tiles0 = (cnt0 + TILE_E - 1) / TILE_E;
    const int tiles1 = (cnt1 + TILE_E - 1) / TILE_E;
    const int total = tiles0 + tiles1;

    // gather tile wi into buffer p (pure per-thread; no syncs)
    auto gather = [&](int wi, int p) {
        int b = (wi >= tiles0);
        int cnt = b ? cnt1 : cnt0;
        int t0 = (b ? (wi - tiles0) : wi) * TILE_E;
        int e = tid >> 1, r = tid & 1;
        int slot = t0 + e;
        int ae = (slot < cnt) ? g_active[(size_t)b * EE + slot] : 0;
        if (r == 0) s_ae[p * 64 + e] = ae;
        int2 pr = __ldg((const int2*)eidx + (size_t)b * EE + ae);
        const float4* h1p = (const float4*)(g_hnodes + ((size_t)b * NN + pr.x) * DD);
        const float4* h2p = (const float4*)(g_hnodes + ((size_t)b * NN + pr.y) * DD);
        float2* sh = s_h + p * HBUF;
#pragma unroll
        for (int i = 0; i < 8; i++) {
            int q = r + 2 * i;
            float4 a = h1p[q], c = h2p[q];
            int k = q * 4;
            sh[(k + 0) * SHP + e] = make_float2(a.x + c.x, a.x - c.x);
            sh[(k + 1) * SHP + e] = make_float2(a.y + c.y, a.y - c.y);
            sh[(k + 2) * SHP + e] = make_float2(a.z + c.z, a.z - c.z);
            sh[(k + 3) * SHP + e] = make_float2(a.w + c.w, a.w - c.w);
        }
    };

    int wi = blockIdx.x;
    int p = 0;
    if (wi < total) gather(wi, 0);

    for (; wi < total; wi += gridDim.x) {
        __syncthreads();   // gather(wi,p) visible; prior compute on p^1 done
        int wn = wi + gridDim.x;
        if (wn < total) gather(wn, p ^ 1);   // latency hidden by compute below

        int b = (wi >= tiles0);
        int cnt = b ? cnt1 : cnt0;
        int t0 = (b ? (wi - tiles0) : wi) * TILE_E;
        int nval = min(TILE_E, cnt - t0);
        unsigned v0 = (nval >= 32) ? 0xffffffffu : ((1u << nval) - 1u);
        unsigned v1 = (nval >= 64) ? 0xffffffffu
                    : ((nval > 32) ? ((1u << (nval - 32)) - 1u) : 0u);

        const float2* sh = s_h + p * HBUF;
        unsigned long long acc0[16], acc1[16];
#pragma unroll
        for (int j = 0; j < 16; j++) { acc0[j] = 0ull; acc1[j] = 0ull; }

#pragma unroll 2
        for (int k = 0; k < 64; k++) {
            unsigned long long h0 = *(const unsigned long long*)&sh[k * SHP + lane];
            unsigned long long h1 = *(const unsigned long long*)&sh[k * SHP + 32 + lane];
            const ulonglong2* wp = (const ulonglong2*)&s_w[k * 64 + d0];
#pragma unroll
            for (int j2 = 0; j2 < 8; j2++) {
                ulonglong2 ww = wp[j2];
                FMA2(acc0[2 * j2],     h0, ww.x);
                FMA2(acc0[2 * j2 + 1], h0, ww.y);
                FMA2(acc1[2 * j2],     h1, ww.x);
                FMA2(acc1[2 * j2 + 1], h1, ww.y);
            }
        }

        const bool ok0 = (v0 >> lane) & 1u;
        const bool ok1 = (v1 >> lane) & 1u;
        float msum[16];
#pragma unroll
        for (int j = 0; j < 16; j++) msum[j] = 0.0f;

#pragma unroll
        for (int half = 0; half < 2; half++) {
            const unsigned long long* acc = half ? acc1 : acc0;
            const bool msk = half ? ok1 : ok0;
            float hv[16];
#pragma unroll
            for (int j = 0; j < 16; j++) {
                float pp = __uint_as_float((unsigned)(acc[j] & 0xffffffffu));
                float qq = __uint_as_float((unsigned)(acc[j] >> 32));
                float bias = s_be[d0 + j];
                float s = fmaf(0.5f, pp + qq, bias);
                float t = fmaf(0.5f, pp - qq, bias);
                float v = 0.5f * (ftanh(s) + ftanh(t));
                hv[j] = msk ? v : 0.0f;
                msum[j] += hv[j];
            }
            if (msk) {
                int ae = s_ae[p * 64 + half * 32 + lane];
                float4* op = (float4*)(out_policy + ((size_t)b * EE + ae) * DD + d0);
                op[0] = make_float4(hv[0],  hv[1],  hv[2],  hv[3]);
                op[1] = make_float4(hv[4],  hv[5],  hv[6],  hv[7]);
                op[2] = make_float4(hv[8],  hv[9],  hv[10], hv[11]);
                op[3] = make_float4(hv[12], hv[13], hv[14], hv[15]);
            }
        }

#pragma unroll
        for (int j = 0; j < 16; j++) {
            float v = msum[j];
            v += __shfl_xor_sync(0xffffffffu, v, 16);
            v += __shfl_xor_sync(0xffffffffu, v, 8);
            v += __shfl_xor_sync(0xffffffffu, v, 4);
            v += __shfl_xor_sync(0xffffffffu, v, 2);
            v += __shfl_xor_sync(0xffffffffu, v, 1);
            if (lane == 0) s_sum[b * DD + d0 + j] += v;
        }
        p ^= 1;
    }

    __syncthreads();
    if (tid < BB * DD) atomicAdd(&g_sum[tid], s_sum[tid]);
}

// -------- finalize --------
__global__ void k_final(const float* __restrict__ numerical,
                        const float* __restrict__ stage,
                        const float* __restrict__ W1, const float* __restrict__ b1,
                        const float* __restrict__ W2, const float* __restrict__ b2,
                        float* __restrict__ out_value)
{
    __shared__ float t1[BB * H0];
    __shared__ float part[BB * H1];
    int t = threadIdx.x;
    if (t < BB * H0) {
        int b = t / H0, j = t % H0;
        float acc = b1[j];
#pragma unroll
        for (int k = 0; k < NODE_DIM; k++) acc = fmaf(numerical[b * NODE_DIM + k], W1[k * H0 + j], acc);
        t1[t] = ftanh(acc);
    }
    __syncthreads();
    // layer 2: 2 threads per output (split k range), 256 threads cover 128 outputs
    {
        int th = t >> 7;              // 0/1: k-half
        int o  = t & 127;             // output index
        int b = o / H1, j = o % H1;
        float acc = 0.0f;
#pragma unroll 8
        for (int k = th * 64; k < th * 64 + 64; k++)
            acc = fmaf(t1[b * H0 + k], W2[k * H1 + j], acc);
        if (th == 1) part[o] = acc;
        __syncthreads();
        if (th == 0) {
            float s = acc + part[o] + b2[j];
            out_value[b * 130 + j] = ftanh(s);
            out_value[b * 130 + 64 + j] = g_sum[b * DD + j] / (float)g_cnt[b];
        }
    }
    if (t < BB * 2) {
        int b = t >> 1, s2 = t & 1;
        out_value[b * 130 + 128 + s2] = stage[b * 2 + s2];
    }
}

// -------- launch --------
extern "C" void kernel_launch(void* const* d_in, const int* in_sizes, int n_in,
                              void* d_out, int out_size) {
    (void)in_sizes; (void)n_in; (void)out_size;
    const float* numerical    = (const float*)d_in[0];
    const float* node_feature = (const float*)d_in[1];
    const int*   edge_index   = (const int*)d_in[2];
    const void*  edge_mask    = d_in[3];
    const float* stage        = (const float*)d_in[4];
    const float* W1 = (const float*)d_in[5];
    const float* b1 = (const float*)d_in[6];
    const float* W2 = (const float*)d_in[7];
    const float* b2 = (const float*)d_in[8];
    const float* Wn = (const float*)d_in[9];
    const float* bn = (const float*)d_in[10];
    const float* We = (const float*)d_in[11];
    const float* be = (const float*)d_in[12];

    float* out        = (float*)d_out;
    float* out_policy = out;
    float* out_value  = out + (size_t)BB * EE * DD;

    cudaFuncSetAttribute(k_edges, cudaFuncAttributeMaxDynamicSharedMemorySize, EDGE_SMEM);

    k_init <<<1, 256>>>((const unsigned int*)edge_mask);
    k_cntA <<<250, 128>>>(edge_mask);
    k_scanB<<<1, 1024>>>();
    k_scatC<<<250, 128>>>(edge_mask);
    k_zero <<<12500, 256>>>(edge_mask, out_policy);
    k_nodes<<<2960, 256>>>(node_feature, Wn, bn);
    k_edges<<<296, 128, EDGE_SMEM>>>(We, be, edge_index, out_policy);
    k_final<<<1, 256>>>(numerical, stage, W1, b1, W2, b2, out_value);
}

// round 10
// speedup vs baseline: 3.2361x; 1.1306x over previous
#include <cuda_runtime.h>
#include <cuda_bf16.h>
#include <math.h>
#include <stdint.h>

#define BB 2
#define NN 100000
#define EE 400000
#define NODE_DIM 32
#define DD 64
#define H0 128
#define H1 64
#define TILE_E 128
#define W_PER_B 500
#define SPAN 800

// -------- device scratch --------
__device__ __align__(16) __nv_bfloat16 g_hn_hi[(size_t)BB * NN * DD];  // 25.6 MB
__device__ __align__(16) __nv_bfloat16 g_hn_lo[(size_t)BB * NN * DD];  // 25.6 MB
__device__ int   g_active[(size_t)BB * EE];
__device__ int   g_wcnt[BB * W_PER_B];
__device__ int   g_wbase[BB * W_PER_B];
__device__ float g_sum[BB * DD];
__device__ int   g_cnt[BB];
__device__ int   g_mask_mode;

__device__ __forceinline__ float ftanh(float x) {
    float e = __expf(2.0f * x);
    return 1.0f - __fdividef(2.0f, e + 1.0f);
}

__device__ __forceinline__ bool mask_at(const void* m, long long i, int mode) {
    if (mode == 1) return ((const int*)m)[i] != 0;
    if (mode == 2) return ((const float*)m)[i] != 0.0f;
    return ((const unsigned char*)m)[i] != 0;
}

// ======== baseline-PTX helpers (sm_80-era; guaranteed to assemble) ========
__device__ __forceinline__ uint32_t smem_to_u32(const void* p) {
    uint32_t a;
    asm("{ .reg .u64 t; cvta.to.shared.u64 t, %1; cvt.u32.u64 %0, t; }" : "=r"(a) : "l"(p));
    return a;
}
#define CP_ASYNC16(dst, src) asm volatile("cp.async.cg.shared.global [%0], [%1], 16;" :: "r"(dst), "l"(src) : "memory")
#define CP_COMMIT()          asm volatile("cp.async.commit_group;" ::: "memory")
#define CP_WAIT0()           asm volatile("cp.async.wait_group 0;" ::: "memory")

__device__ __forceinline__ void ldsm4(uint32_t* r, uint32_t addr) {
    asm volatile("ldmatrix.sync.aligned.m8n8.x4.shared.b16 {%0,%1,%2,%3}, [%4];"
        : "=r"(r[0]), "=r"(r[1]), "=r"(r[2]), "=r"(r[3]) : "r"(addr));
}
__device__ __forceinline__ void mma16816(float* d, const uint32_t* a, const uint32_t* b) {
    asm volatile("mma.sync.aligned.m16n8k16.row.col.f32.bf16.bf16.f32 "
        "{%0,%1,%2,%3}, {%4,%5,%6,%7}, {%8,%9}, {%0,%1,%2,%3};"
        : "+f"(d[0]), "+f"(d[1]), "+f"(d[2]), "+f"(d[3])
        : "r"(a[0]), "r"(a[1]), "r"(a[2]), "r"(a[3]), "r"(b[0]), "r"(b[1]));
}

// row-major bf16 tile, 128 cols (256B row), 16B chunks swizzled: chunk' = chunk ^ (row&7)
__device__ __forceinline__ void sts_sw(unsigned char* base, int row, int chunk, uint4 v) {
    *(uint4*)(base + row * 256 + (((chunk) ^ (row & 7)) << 4)) = v;
}

__device__ __forceinline__ void split8(const float* x, uint4& hi, uint4& lo) {
    unsigned h[8], l[8];
#pragma unroll
    for (int i = 0; i < 8; i++) {
        __nv_bfloat16 b = __float2bfloat16(x[i]);
        h[i] = (unsigned)__bfloat16_as_ushort(b);
        float r = x[i] - __bfloat162float(b);
        l[i] = (unsigned)__bfloat16_as_ushort(__float2bfloat16(r));
    }
    hi = make_uint4(h[0] | (h[1] << 16), h[2] | (h[3] << 16), h[4] | (h[5] << 16), h[6] | (h[7] << 16));
    lo = make_uint4(l[0] | (l[1] << 16), l[2] | (l[3] << 16), l[4] | (l[5] << 16), l[6] | (l[7] << 16));
}

// ======== small kernels ========
__global__ void k_init(const unsigned int* mask_words) {
    int t = threadIdx.x;
    if (t < BB * DD) g_sum[t] = 0.0f;
    __shared__ int s_notint, s_notfl;
    if (t == 0) { s_notint = 0; s_notfl = 0; }
    __syncthreads();
    int ni = 0, nf = 0;
    for (int i = t; i < 1024; i += blockDim.x) {
        unsigned w = mask_words[i];
        if (w > 1u) ni = 1;
        if (w != 0u && w != 0x3F800000u) nf = 1;
    }
    if (ni) atomicOr(&s_notint, 1);
    if (nf) atomicOr(&s_notfl, 1);
    __syncthreads();
    if (t == 0) g_mask_mode = (!s_notint) ? 1 : ((!s_notfl) ? 2 : 0);
}

__global__ void k_cntA(const void* __restrict__ mask) {
    const int mode = g_mask_mode;
    int wg = blockIdx.x * 4 + (threadIdx.x >> 5);
    int lane = threadIdx.x & 31;
    int b = wg / W_PER_B;
    long long base = (long long)b * EE + (long long)(wg % W_PER_B) * SPAN;
    int cnt = 0;
#pragma unroll 5
    for (int c = 0; c < SPAN / 32; c++) {
        bool m = mask_at(mask, base + c * 32 + lane, mode);
        cnt += __popc(__ballot_sync(0xffffffffu, m));
    }
    if (lane == 0) g_wcnt[wg] = cnt;
}

__global__ void k_scanB() {
    __shared__ int s[1024];
    int t = threadIdx.x, tl = t & 511, b = t >> 9;
    int v = (tl < W_PER_B) ? g_wcnt[b * W_PER_B + tl] : 0;
    s[t] = v;
    __syncthreads();
#pragma unroll
    for (int off = 1; off < 512; off <<= 1) {
        int add = (tl >= off) ? s[t - off] : 0;
        __syncthreads();
        s[t] += add;
        __syncthreads();
    }
    if (tl < W_PER_B) g_wbase[b * W_PER_B + tl] = s[t] - v;
    if (tl == W_PER_B - 1) g_cnt[b] = s[t];
}

__global__ void k_scatC(const void* __restrict__ mask) {
    const int mode = g_mask_mode;
    int wg = blockIdx.x * 4 + (threadIdx.x >> 5);
    int lane = threadIdx.x & 31;
    int b = wg / W_PER_B;
    long long ebase = (long long)(wg % W_PER_B) * SPAN;
    long long gbase = (long long)b * EE + ebase;
    int running = g_wbase[wg];
#pragma unroll 5
    for (int c = 0; c < SPAN / 32; c++) {
        long long i = gbase + c * 32 + lane;
        int il = (int)(ebase + c * 32 + lane);
        bool m = mask_at(mask, i, mode);
        unsigned bal = __ballot_sync(0xffffffffu, m);
        int rank = __popc(bal & ((1u << lane) - 1u));
        if (m) g_active[(size_t)b * EE + running + rank] = il;
        running += __popc(bal);
    }
}

__global__ void k_zero(const void* __restrict__ mask, float* __restrict__ out_policy) {
    const int mode = g_mask_mode;
    const float4 z = make_float4(0.f, 0.f, 0.f, 0.f);
    long long stride = (long long)gridDim.x * blockDim.x;
    for (long long i = (long long)blockIdx.x * blockDim.x + threadIdx.x;
         i < (long long)BB * EE * 16; i += stride) {
        long long e = i >> 4;
        if (!mask_at(mask, e, mode)) ((float4*)out_policy)[i] = z;
    }
}

// node MLP -> tanh -> bf16 hi/lo split arrays
__global__ void k_nodes(const float* __restrict__ nf,
                        const float* __restrict__ Wn,
                        const float* __restrict__ bn) {
    __shared__ float2 ws[NODE_DIM][32];
    __shared__ float2 bs[32];
    int tid = threadIdx.x, lane = tid & 31, w = tid >> 5;
    for (int i = tid; i < NODE_DIM * 32; i += blockDim.x) {
        int k = i >> 5, j = i & 31;
        ws[k][j] = make_float2(Wn[k * DD + j], Wn[k * DD + j + 32]);
    }
    if (tid < 32) bs[tid] = make_float2(bn[tid], bn[tid + 32]);
    __syncthreads();
    const int nrows = BB * NN;
    const int warps = (blockDim.x >> 5) * gridDim.x;
    for (int row = blockIdx.x * (blockDim.x >> 5) + w; row < nrows; row += warps) {
        float x = nf[(size_t)row * NODE_DIM + lane];
        float2 acc = bs[lane];
#pragma unroll
        for (int k = 0; k < NODE_DIM; k++) {
            float v = __shfl_sync(0xffffffffu, x, k);
            float2 wv = ws[k][lane];
            acc.x = fmaf(v, wv.x, acc.x);
            acc.y = fmaf(v, wv.y, acc.y);
        }
        float v0 = ftanh(acc.x), v1 = ftanh(acc.y);
        __nv_bfloat16 h0 = __float2bfloat16(v0);
        __nv_bfloat16 h1 = __float2bfloat16(v1);
        __nv_bfloat16 l0 = __float2bfloat16(v0 - __bfloat162float(h0));
        __nv_bfloat16 l1 = __float2bfloat16(v1 - __bfloat162float(h1));
        __nv_bfloat16* oh = g_hn_hi + (size_t)row * DD;
        __nv_bfloat16* ol = g_hn_lo + (size_t)row * DD;
        oh[lane] = h0; oh[lane + 32] = h1;
        ol[lane] = l0; ol[lane + 32] = l1;
    }
}

// ======== edge kernel: mma.sync bf16 3-split, cp.async gather ========
// smem layout (bytes):
//   0     : s_ae[2][128] (1024)
//   1024  : s_sum[128] f32 (512)
//   1536  : s_be[64] f32 (256)
//   2048  : BHI 32KB   34816: BLO 32KB
//   67584 : AHI[0] 32KB, 100352: AHI[1]
//   133120: ALO[0] 32KB, 165888: ALO[1]
#define SM_AE   0
#define SM_SUM  1024
#define SM_BE   1536
#define SM_BHI  2048
#define SM_BLO  34816
#define SM_AHI  67584
#define SM_ALO  133120
#define EDGE_SMEM 198656

__global__ void __launch_bounds__(256, 1) k_edges(
    const float* __restrict__ We, const float* __restrict__ be,
    const int* __restrict__ eidx,
    float* __restrict__ out_policy)
{
    extern __shared__ unsigned char dsm[];
    const uint32_t smem_base = smem_to_u32(dsm);
    const int tid = threadIdx.x;
    const int lane = tid & 31, wid = tid >> 5;
    int*   s_ae  = (int*)(dsm + SM_AE);
    float* s_sum = (float*)(dsm + SM_SUM);
    float* s_be  = (float*)(dsm + SM_BE);

    // ---- B prep: B[n(row 0..127)][k 0..127]; n<64: We[k][n]; n>=64: We[k^64][n-64]
    {
        int n = tid & 127, r2 = tid >> 7, np = n & 63;
#pragma unroll 1
        for (int g = 0; g < 8; g++) {
            int k0 = 64 * r2 + 8 * g;
            float wv[8];
#pragma unroll
            for (int j = 0; j < 8; j++) {
                int k = k0 + j;
                int kk = (n < 64) ? k : (k ^ 64);
                wv[j] = We[kk * 64 + np];
            }
            uint4 hi, lo;
            split8(wv, hi, lo);
            sts_sw(dsm + SM_BHI, n, k0 >> 3, hi);
            sts_sw(dsm + SM_BLO, n, k0 >> 3, lo);
        }
    }
    if (tid < 64) s_be[tid] = be[tid];
    if (tid < 128) s_sum[tid] = 0.0f;

    const int cnt0 = g_cnt[0], cnt1 = g_cnt[1];
    const int tiles0 = (cnt0 + TILE_E - 1) / TILE_E;
    const int tiles1 = (cnt1 + TILE_E - 1) / TILE_E;
    const int total = tiles0 + tiles1;

    // warp tiling: 4 m-groups x 2 n-groups
    const int mg = wid >> 1, ng = wid & 1;
    const int sw = lane & 7;

    // gather tile ti into A buffer p via cp.async (16B copies, no conversion)
    auto gather = [&](int ti, int p) {
        int b = (ti >= tiles0);
        int cnt = b ? cnt1 : cnt0;
        int t0 = (b ? (ti - tiles0) : ti) * TILE_E;
        int e = tid >> 1, r = tid & 1;          // r=0: h1 (chunks 0-7), r=1: h2 (chunks 8-15)
        int slot = t0 + e;
        int ae = (slot < cnt) ? __ldg(&g_active[(size_t)b * EE + slot]) : 0;
        if (r == 0) s_ae[p * 128 + e] = ae;
        int2 pr = __ldg((const int2*)eidx + (size_t)b * EE + ae);
        int node = r ? pr.y : pr.x;
        const char* srcH = (const char*)g_hn_hi + ((size_t)b * NN + node) * 128;
        const char* srcL = (const char*)g_hn_lo + ((size_t)b * NN + node) * 128;
        uint32_t dstH = smem_base + SM_AHI + p * 32768 + e * 256;
        uint32_t dstL = smem_base + SM_ALO + p * 32768 + e * 256;
        int esw = e & 7;
#pragma unroll
        for (int cl = 0; cl < 8; cl++) {
            int c = 8 * r + cl;
            uint32_t off = (uint32_t)((c ^ esw) << 4);
            CP_ASYNC16(dstH + off, srcH + cl * 16);
            CP_ASYNC16(dstL + off, srcL + cl * 16);
        }
    };

    int p = 0;
    if (blockIdx.x < total) gather(blockIdx.x, 0);
    CP_COMMIT(); CP_WAIT0();
    __syncthreads();

    // per-thread bias regs: cols = ng*32 + 8j + 2*(lane&3) + {0,1}
    float ber[4][2];
#pragma unroll
    for (int j = 0; j < 4; j++) {
        int c = ng * 32 + 8 * j + 2 * (lane & 3);
        ber[j][0] = s_be[c];
        ber[j][1] = s_be[c + 1];
    }

    // per-lane ldmatrix address components
    // A: row = mg*32 + mt2*16 + (lane&15); chunk = 2kt + (lane>>4)
    const uint32_t rowA_off = (uint32_t)((mg * 32 + (lane & 15)) * 256);
    const int chA = lane >> 4;
    // B: row = n0 + (lane&7) + ((lane>>4)<<3); chunk = 2kt + ((lane>>3)&1)
    const int rowB_add = (lane & 7) + ((lane >> 4) << 3);
    const int chB = (lane >> 3) & 1;

    for (int ti = blockIdx.x; ti < total; ti += gridDim.x) {
        const int b = (ti >= tiles0);
        const int cnt = b ? cnt1 : cnt0;
        const int t0 = (b ? (ti - tiles0) : ti) * TILE_E;

        int tn = ti + gridDim.x;
        if (tn < total) gather(tn, p ^ 1);
        CP_COMMIT();

        // ---- GEMM: D[128 edges][128] = A[128][128k] * B^T, 3-split bf16
        float d[2][8][4];
#pragma unroll
        for (int a = 0; a < 2; a++)
#pragma unroll
            for (int s = 0; s < 8; s++)
#pragma unroll
                for (int q = 0; q < 4; q++) d[a][s][q] = 0.0f;

#pragma unroll
        for (int split = 0; split < 3; split++) {
            uint32_t Abase = smem_base + ((split < 2) ? SM_AHI : SM_ALO) + p * 32768;
            uint32_t Bbase = smem_base + ((split == 1) ? SM_BLO : SM_BHI);
#pragma unroll
            for (int kt = 0; kt < 8; kt++) {
                uint32_t bb[4][4];
#pragma unroll
                for (int pi = 0; pi < 4; pi++) {
                    int n0 = ng * 32 + ((pi & 1) ? 16 : 0) + ((pi & 2) ? 64 : 0);
                    int rowB = n0 + rowB_add;
                    uint32_t addr = Bbase + rowB * 256 + (uint32_t)((((2 * kt + chB) ^ (rowB & 7))) << 4);
                    ldsm4(bb[pi], addr);
                }
#pragma unroll
                for (int mt2 = 0; mt2 < 2; mt2++) {
                    uint32_t aa[4];
                    uint32_t addrA = Abase + rowA_off + (uint32_t)(mt2 * 16 * 256)
                                   + (uint32_t)(((2 * kt + chA) ^ sw) << 4);
                    ldsm4(aa, addrA);
#pragma unroll
                    for (int pi = 0; pi < 4; pi++) {
                        mma16816(d[mt2][2 * pi],     aa, &bb[pi][0]);
                        mma16816(d[mt2][2 * pi + 1], aa, &bb[pi][2]);
                    }
                }
            }
        }

        // ---- epilogue: v = 0.5*(tanh(e12)+tanh(e21)); slots 0-3 = e12, 4-7 = e21
        float msum[4][2];
#pragma unroll
        for (int j = 0; j < 4; j++) { msum[j][0] = 0.0f; msum[j][1] = 0.0f; }

#pragma unroll
        for (int mt2 = 0; mt2 < 2; mt2++) {
            int rl0 = mg * 32 + mt2 * 16 + (lane >> 2);
            int rl1 = rl0 + 8;
            bool val0 = (t0 + rl0) < cnt;
            bool val1 = (t0 + rl1) < cnt;
            int ae0 = s_ae[p * 128 + rl0];
            int ae1 = s_ae[p * 128 + rl1];
            float* o0 = out_policy + ((size_t)b * EE + ae0) * DD;
            float* o1 = out_policy + ((size_t)b * EE + ae1) * DD;
#pragma unroll
            for (int j = 0; j < 4; j++) {
                const float* sD = d[mt2][j];
                const float* tD = d[mt2][4 + j];
                float v00 = 0.5f * (ftanh(sD[0] + ber[j][0]) + ftanh(tD[0] + ber[j][0]));
                float v01 = 0.5f * (ftanh(sD[1] + ber[j][1]) + ftanh(tD[1] + ber[j][1]));
                float v10 = 0.5f * (ftanh(sD[2] + ber[j][0]) + ftanh(tD[2] + ber[j][0]));
                float v11 = 0.5f * (ftanh(sD[3] + ber[j][1]) + ftanh(tD[3] + ber[j][1]));
                if (!val0) { v00 = 0.0f; v01 = 0.0f; }
                if (!val1) { v10 = 0.0f; v11 = 0.0f; }
                int cb = ng * 32 + 8 * j + 2 * (lane & 3);
                if (val0) *(float2*)(o0 + cb) = make_float2(v00, v01);
                if (val1) *(float2*)(o1 + cb) = make_float2(v10, v11);
                msum[j][0] += v00 + v10;
                msum[j][1] += v01 + v11;
            }
        }
        // reduce over rows: lanes with equal (lane&3) share cols
#pragma unroll
        for (int j = 0; j < 4; j++) {
#pragma unroll
            for (int i = 0; i < 2; i++) {
                float v = msum[j][i];
                v += __shfl_xor_sync(0xffffffffu, v, 4);
                v += __shfl_xor_sync(0xffffffffu, v, 8);
                v += __shfl_xor_sync(0xffffffffu, v, 16);
                msum[j][i] = v;
            }
        }
        if (lane < 4) {
#pragma unroll
            for (int j = 0; j < 4; j++) {
                int c = ng * 32 + 8 * j + 2 * lane;
                atomicAdd(&s_sum[b * DD + c],     msum[j][0]);
                atomicAdd(&s_sum[b * DD + c + 1], msum[j][1]);
            }
        }

        CP_WAIT0();
        __syncthreads();
        p ^= 1;
    }

    __syncthreads();
    if (tid < 128) atomicAdd(&g_sum[tid], s_sum[tid]);
}

// -------- finalize --------
__global__ void k_final(const float* __restrict__ numerical,
                        const float* __restrict__ stage,
                        const float* __restrict__ W1, const float* __restrict__ b1,
                        const float* __restrict__ W2, const float* __restrict__ b2,
                        float* __restrict__ out_value)
{
    __shared__ float t1[BB * H0];
    __shared__ float part[BB * H1];
    int t = threadIdx.x;
    if (t < BB * H0) {
        int b = t / H0, j = t % H0;
        float acc = b1[j];
#pragma unroll
        for (int k = 0; k < NODE_DIM; k++) acc = fmaf(numerical[b * NODE_DIM + k], W1[k * H0 + j], acc);
        t1[t] = ftanh(acc);
    }
    __syncthreads();
    {
        int th = t >> 7;
        int o  = t & 127;
        int b = o / H1, j = o % H1;
        float acc = 0.0f;
#pragma unroll 8
        for (int k = th * 64; k < th * 64 + 64; k++)
            acc = fmaf(t1[b * H0 + k], W2[k * H1 + j], acc);
        if (th == 1) part[o] = acc;
        __syncthreads();
        if (th == 0) {
            float s = acc + part[o] + b2[j];
            out_value[b * 130 + j] = ftanh(s);
            out_value[b * 130 + 64 + j] = g_sum[b * DD + j] / (float)g_cnt[b];
        }
    }
    if (t < BB * 2) {
        int b = t >> 1, s2 = t & 1;
        out_value[b * 130 + 128 + s2] = stage[b * 2 + s2];
    }
}

// -------- launch --------
extern "C" void kernel_launch(void* const* d_in, const int* in_sizes, int n_in,
                              void* d_out, int out_size) {
    (void)in_sizes; (void)n_in; (void)out_size;
    const float* numerical    = (const float*)d_in[0];
    const float* node_feature = (const float*)d_in[1];
    const int*   edge_index   = (const int*)d_in[2];
    const void*  edge_mask    = d_in[3];
    const float* stage        = (const float*)d_in[4];
    const float* W1 = (const float*)d_in[5];
    const float* b1 = (const float*)d_in[6];
    const float* W2 = (const float*)d_in[7];
    const float* b2 = (const float*)d_in[8];
    const float* Wn = (const float*)d_in[9];
    const float* bn = (const float*)d_in[10];
    const float* We = (const float*)d_in[11];
    const float* be = (const float*)d_in[12];

    float* out        = (float*)d_out;
    float* out_policy = out;
    float* out_value  = out + (size_t)BB * EE * DD;

    cudaFuncSetAttribute(k_edges, cudaFuncAttributeMaxDynamicSharedMemorySize, EDGE_SMEM);

    k_init <<<1, 256>>>((const unsigned int*)edge_mask);
    k_cntA <<<250, 128>>>(edge_mask);
    k_scanB<<<1, 1024>>>();
    k_scatC<<<250, 128>>>(edge_mask);
    k_zero <<<12500, 256>>>(edge_mask, out_policy);
    k_nodes<<<2960, 256>>>(node_feature, Wn, bn);
    k_edges<<<148, 256, EDGE_SMEM>>>(We, be, edge_index, out_policy);
    k_final<<<1, 256>>>(numerical, stage, W1, b1, W2, b2, out_value);
}

// round 11
// speedup vs baseline: 3.2774x; 1.0128x over previous
#include <cuda_runtime.h>
#include <cuda_bf16.h>
#include <math.h>
#include <stdint.h>

#define BB 2
#define NN 100000
#define EE 400000
#define NODE_DIM 32
#define DD 64
#define H0 128
#define H1 64
#define TILE_E 128
#define W_PER_B 500
#define SPAN 800

// -------- device scratch --------
// combined node rows: [hi 64 bf16 | lo 64 bf16] = 256B per node
__device__ __align__(256) __nv_bfloat16 g_hn[(size_t)BB * NN * 128];   // 51.2 MB
__device__ int   g_active[(size_t)BB * EE];
__device__ int   g_wcnt[BB * W_PER_B];
__device__ int   g_wbase[BB * W_PER_B];
__device__ float g_sum[BB * DD];
__device__ int   g_cnt[BB];
__device__ int   g_mask_mode;

__device__ __forceinline__ float ftanh(float x) {
    float e = __expf(2.0f * x);
    return 1.0f - __fdividef(2.0f, e + 1.0f);
}

__device__ __forceinline__ bool mask_at(const void* m, long long i, int mode) {
    if (mode == 1) return ((const int*)m)[i] != 0;
    if (mode == 2) return ((const float*)m)[i] != 0.0f;
    return ((const unsigned char*)m)[i] != 0;
}

// ======== PTX helpers (baseline sm_90-era; assemble on sm_103) ========
__device__ __forceinline__ uint32_t smem_to_u32(const void* p) {
    uint32_t a;
    asm("{ .reg .u64 t; cvta.to.shared.u64 t, %1; cvt.u32.u64 %0, t; }" : "=r"(a) : "l"(p));
    return a;
}
#define MBARRIER_INIT(mb, c) asm volatile("mbarrier.init.shared.b64 [%0], %1;" :: "r"((uint32_t)(mb)), "r"((uint32_t)(c)) : "memory")
#define MBARRIER_ARRIVE_EXPECT(mb, n) asm volatile("mbarrier.arrive.expect_tx.shared.b64 _, [%0], %1;" :: "r"((uint32_t)(mb)), "r"((uint32_t)(n)) : "memory")
#define CP_BULK(dst, src, n, mb) asm volatile( \
    "cp.async.bulk.shared::cta.global.mbarrier::complete_tx::bytes [%0], [%1], %2, [%3];" \
    :: "r"((uint32_t)(dst)), "l"(src), "r"((uint32_t)(n)), "r"((uint32_t)(mb)) : "memory")
#define MBARRIER_WAIT_PARITY(mb, ph) do { \
    uint32_t _mb = (uint32_t)(mb), _ph = (uint32_t)(ph), _done; \
    asm volatile("{\n\t.reg .pred p;\n\tmbarrier.try_wait.parity.acquire.cta.shared::cta.b64 p, [%1], %2;\n\tselp.b32 %0, 1, 0, p;\n\t}" \
        : "=r"(_done) : "r"(_mb), "r"(_ph) : "memory"); \
    if (!_done) { \
        asm volatile("{\n\t.reg .pred P1;\n\tWL_%=:\n\tmbarrier.try_wait.parity.acquire.cta.shared::cta.b64 P1, [%0], %1, 0x989680;\n\t@P1 bra.uni WD_%=;\n\tbra.uni WL_%=;\n\tWD_%=:\n\t}" \
            :: "r"(_mb), "r"(_ph) : "memory"); \
    } } while (0)

__device__ __forceinline__ void ldsm4(uint32_t* r, uint32_t addr) {
    asm volatile("ldmatrix.sync.aligned.m8n8.x4.shared.b16 {%0,%1,%2,%3}, [%4];"
        : "=r"(r[0]), "=r"(r[1]), "=r"(r[2]), "=r"(r[3]) : "r"(addr));
}
__device__ __forceinline__ void mma16816(float* d, const uint32_t* a, const uint32_t* b) {
    asm volatile("mma.sync.aligned.m16n8k16.row.col.f32.bf16.bf16.f32 "
        "{%0,%1,%2,%3}, {%4,%5,%6,%7}, {%8,%9}, {%0,%1,%2,%3};"
        : "+f"(d[0]), "+f"(d[1]), "+f"(d[2]), "+f"(d[3])
        : "r"(a[0]), "r"(a[1]), "r"(a[2]), "r"(a[3]), "r"(b[0]), "r"(b[1]));
}

// B tile: row-major bf16, 128 cols (256B row), 16B chunks XOR-swizzled
__device__ __forceinline__ void sts_sw(unsigned char* base, int row, int chunk, uint4 v) {
    *(uint4*)(base + row * 256 + (((chunk) ^ (row & 7)) << 4)) = v;
}

__device__ __forceinline__ void split8(const float* x, uint4& hi, uint4& lo) {
    unsigned h[8], l[8];
#pragma unroll
    for (int i = 0; i < 8; i++) {
        __nv_bfloat16 b = __float2bfloat16(x[i]);
        h[i] = (unsigned)__bfloat16_as_ushort(b);
        float r = x[i] - __bfloat162float(b);
        l[i] = (unsigned)__bfloat16_as_ushort(__float2bfloat16(r));
    }
    hi = make_uint4(h[0] | (h[1] << 16), h[2] | (h[3] << 16), h[4] | (h[5] << 16), h[6] | (h[7] << 16));
    lo = make_uint4(l[0] | (l[1] << 16), l[2] | (l[3] << 16), l[4] | (l[5] << 16), l[6] | (l[7] << 16));
}

// ======== small kernels ========
__global__ void k_init(const unsigned int* mask_words) {
    int t = threadIdx.x;
    if (t < BB * DD) g_sum[t] = 0.0f;
    __shared__ int s_notint, s_notfl;
    if (t == 0) { s_notint = 0; s_notfl = 0; }
    __syncthreads();
    int ni = 0, nf = 0;
    for (int i = t; i < 1024; i += blockDim.x) {
        unsigned w = mask_words[i];
        if (w > 1u) ni = 1;
        if (w != 0u && w != 0x3F800000u) nf = 1;
    }
    if (ni) atomicOr(&s_notint, 1);
    if (nf) atomicOr(&s_notfl, 1);
    __syncthreads();
    if (t == 0) g_mask_mode = (!s_notint) ? 1 : ((!s_notfl) ? 2 : 0);
}

__global__ void k_cntA(const void* __restrict__ mask) {
    const int mode = g_mask_mode;
    int wg = blockIdx.x * 4 + (threadIdx.x >> 5);
    int lane = threadIdx.x & 31;
    int b = wg / W_PER_B;
    long long base = (long long)b * EE + (long long)(wg % W_PER_B) * SPAN;
    int cnt = 0;
#pragma unroll 5
    for (int c = 0; c < SPAN / 32; c++) {
        bool m = mask_at(mask, base + c * 32 + lane, mode);
        cnt += __popc(__ballot_sync(0xffffffffu, m));
    }
    if (lane == 0) g_wcnt[wg] = cnt;
}

__global__ void k_scanB() {
    __shared__ int s[1024];
    int t = threadIdx.x, tl = t & 511, b = t >> 9;
    int v = (tl < W_PER_B) ? g_wcnt[b * W_PER_B + tl] : 0;
    s[t] = v;
    __syncthreads();
#pragma unroll
    for (int off = 1; off < 512; off <<= 1) {
        int add = (tl >= off) ? s[t - off] : 0;
        __syncthreads();
        s[t] += add;
        __syncthreads();
    }
    if (tl < W_PER_B) g_wbase[b * W_PER_B + tl] = s[t] - v;
    if (tl == W_PER_B - 1) g_cnt[b] = s[t];
}

__global__ void k_scatC(const void* __restrict__ mask) {
    const int mode = g_mask_mode;
    int wg = blockIdx.x * 4 + (threadIdx.x >> 5);
    int lane = threadIdx.x & 31;
    int b = wg / W_PER_B;
    long long ebase = (long long)(wg % W_PER_B) * SPAN;
    long long gbase = (long long)b * EE + ebase;
    int running = g_wbase[wg];
#pragma unroll 5
    for (int c = 0; c < SPAN / 32; c++) {
        long long i = gbase + c * 32 + lane;
        int il = (int)(ebase + c * 32 + lane);
        bool m = mask_at(mask, i, mode);
        unsigned bal = __ballot_sync(0xffffffffu, m);
        int rank = __popc(bal & ((1u << lane) - 1u));
        if (m) g_active[(size_t)b * EE + running + rank] = il;
        running += __popc(bal);
    }
}

__global__ void k_zero(const void* __restrict__ mask, float* __restrict__ out_policy) {
    const int mode = g_mask_mode;
    const float4 z = make_float4(0.f, 0.f, 0.f, 0.f);
    long long stride = (long long)gridDim.x * blockDim.x;
    for (long long i = (long long)blockIdx.x * blockDim.x + threadIdx.x;
         i < (long long)BB * EE * 16; i += stride) {
        long long e = i >> 4;
        if (!mask_at(mask, e, mode)) ((float4*)out_policy)[i] = z;
    }
}

// node MLP -> tanh -> combined [hi|lo] bf16 rows
__global__ void k_nodes(const float* __restrict__ nf,
                        const float* __restrict__ Wn,
                        const float* __restrict__ bn) {
    __shared__ float2 ws[NODE_DIM][32];
    __shared__ float2 bs[32];
    int tid = threadIdx.x, lane = tid & 31, w = tid >> 5;
    for (int i = tid; i < NODE_DIM * 32; i += blockDim.x) {
        int k = i >> 5, j = i & 31;
        ws[k][j] = make_float2(Wn[k * DD + j], Wn[k * DD + j + 32]);
    }
    if (tid < 32) bs[tid] = make_float2(bn[tid], bn[tid + 32]);
    __syncthreads();
    const int nrows = BB * NN;
    const int warps = (blockDim.x >> 5) * gridDim.x;
    for (int row = blockIdx.x * (blockDim.x >> 5) + w; row < nrows; row += warps) {
        float x = nf[(size_t)row * NODE_DIM + lane];
        float2 acc = bs[lane];
#pragma unroll
        for (int k = 0; k < NODE_DIM; k++) {
            float v = __shfl_sync(0xffffffffu, x, k);
            float2 wv = ws[k][lane];
            acc.x = fmaf(v, wv.x, acc.x);
            acc.y = fmaf(v, wv.y, acc.y);
        }
        float v0 = ftanh(acc.x), v1 = ftanh(acc.y);
        __nv_bfloat16 h0 = __float2bfloat16(v0);
        __nv_bfloat16 h1 = __float2bfloat16(v1);
        __nv_bfloat16 l0 = __float2bfloat16(v0 - __bfloat162float(h0));
        __nv_bfloat16 l1 = __float2bfloat16(v1 - __bfloat162float(h1));
        __nv_bfloat16* o = g_hn + (size_t)row * 128;
        o[lane] = h0;      o[lane + 32] = h1;       // hi half
        o[64 + lane] = l0; o[96 + lane] = l1;       // lo half
    }
}

// ======== edge kernel: mma.sync bf16 3-split + cp.async.bulk gather ========
// smem (bytes):
//   0    : s_ae[2][128] (1024)
//   1024 : s_sum[128] f32 (512)
//   1536 : s_be[64] f32 (256)
//   1792 : mbar[2] u64 (16)
//   2048 : BHI 32KB    34816: BLO 32KB
//   67584: Abuf0 (hi 128x272 = 34816, lo 128x272 = 34816)
//   137216: Abuf1 (same)
//   end 206848
#define SM_AE   0
#define SM_SUM  1024
#define SM_BE   1536
#define SM_MBAR 1792
#define SM_BHI  2048
#define SM_BLO  34816
#define SM_A0   67584
#define SM_A1   137216
#define A_LO_OFF 34816
#define A_PITCH 272
#define EDGE_SMEM 206848

__global__ void __launch_bounds__(256, 1) k_edges(
    const float* __restrict__ We, const float* __restrict__ be,
    const int* __restrict__ eidx,
    float* __restrict__ out_policy)
{
    extern __shared__ unsigned char dsm[];
    const uint32_t smem_base = smem_to_u32(dsm);
    const int tid = threadIdx.x;
    const int lane = tid & 31, wid = tid >> 5;
    int*   s_ae  = (int*)(dsm + SM_AE);
    float* s_sum = (float*)(dsm + SM_SUM);
    float* s_be  = (float*)(dsm + SM_BE);

    // ---- B prep: B[n][k]; n<64: We[k][n]; n>=64: We[k^64][n-64] (bf16 hi/lo)
    {
        int n = tid & 127, r2 = tid >> 7, np = n & 63;
#pragma unroll 1
        for (int g = 0; g < 8; g++) {
            int k0 = 64 * r2 + 8 * g;
            float wv[8];
#pragma unroll
            for (int j = 0; j < 8; j++) {
                int k = k0 + j;
                int kk = (n < 64) ? k : (k ^ 64);
                wv[j] = We[kk * 64 + np];
            }
            uint4 hi, lo;
            split8(wv, hi, lo);
            sts_sw(dsm + SM_BHI, n, k0 >> 3, hi);
            sts_sw(dsm + SM_BLO, n, k0 >> 3, lo);
        }
    }
    if (tid < 64) s_be[tid] = be[tid];
    if (tid < 128) s_sum[tid] = 0.0f;
    if (tid == 0) {
        MBARRIER_INIT(smem_base + SM_MBAR, 128);
        MBARRIER_INIT(smem_base + SM_MBAR + 8, 128);
    }
    __syncthreads();

    const int cnt0 = g_cnt[0], cnt1 = g_cnt[1];
    const int tiles0 = (cnt0 + TILE_E - 1) / TILE_E;
    const int tiles1 = (cnt1 + TILE_E - 1) / TILE_E;
    const int total = tiles0 + tiles1;

    const int mg = wid >> 1, ng = wid & 1;

    // gather: tid<128 threads, one edge each; 4 x 128B bulk copies
    auto gather = [&](int ti, int p) {
        if (tid >= 128) return;
        int b = (ti >= tiles0);
        int cnt = b ? cnt1 : cnt0;
        int t0 = (b ? (ti - tiles0) : ti) * TILE_E;
        int slot = t0 + tid;
        int ae = (slot < cnt) ? __ldg(&g_active[(size_t)b * EE + slot]) : 0;
        s_ae[p * 128 + tid] = ae;
        int2 pr = __ldg((const int2*)eidx + (size_t)b * EE + ae);
        uint32_t mb = smem_base + SM_MBAR + p * 8;
        MBARRIER_ARRIVE_EXPECT(mb, 512u);
        const char* s1 = (const char*)g_hn + ((size_t)b * NN + pr.x) * 256;
        const char* s2 = (const char*)g_hn + ((size_t)b * NN + pr.y) * 256;
        uint32_t dhi = smem_base + (p ? SM_A1 : SM_A0) + tid * A_PITCH;
        uint32_t dlo = dhi + A_LO_OFF;
        CP_BULK(dhi,       s1,       128u, mb);   // h1 hi -> cols 0-63
        CP_BULK(dhi + 128, s2,       128u, mb);   // h2 hi -> cols 64-127
        CP_BULK(dlo,       s1 + 128, 128u, mb);   // h1 lo
        CP_BULK(dlo + 128, s2 + 128, 128u, mb);   // h2 lo
    };

    int p = 0, ph0 = 0, ph1 = 0;
    if (blockIdx.x < total) gather(blockIdx.x, 0);

    // per-thread bias regs: cols = ng*32 + 8j + 2*(lane&3) + {0,1}
    float ber[4][2];
#pragma unroll
    for (int j = 0; j < 4; j++) {
        int c = ng * 32 + 8 * j + 2 * (lane & 3);
        ber[j][0] = s_be[c];
        ber[j][1] = s_be[c + 1];
    }

    // ldmatrix address components
    const uint32_t rowA_off = (uint32_t)((mg * 32 + (lane & 15)) * A_PITCH);
    const int chA = lane >> 4;                 // chunk parity
    const int rowB_add = (lane & 7) + ((lane >> 4) << 3);
    const int chB = (lane >> 3) & 1;

    for (int ti = blockIdx.x; ti < total; ti += gridDim.x) {
        const int b = (ti >= tiles0);
        const int cnt = b ? cnt1 : cnt0;
        const int t0 = (b ? (ti - tiles0) : ti) * TILE_E;

        int tn = ti + gridDim.x;
        if (tn < total) gather(tn, p ^ 1);

        // wait for current tile's A data
        if (p == 0) { MBARRIER_WAIT_PARITY(smem_base + SM_MBAR, ph0); ph0 ^= 1; }
        else        { MBARRIER_WAIT_PARITY(smem_base + SM_MBAR + 8, ph1); ph1 ^= 1; }

        // ---- GEMM: D[128 edges][128] = A[128][128k] * B^T, 3-split bf16
        float d[2][8][4];
#pragma unroll
        for (int a = 0; a < 2; a++)
#pragma unroll
            for (int s = 0; s < 8; s++)
#pragma unroll
                for (int q = 0; q < 4; q++) d[a][s][q] = 0.0f;

        const uint32_t Ab = smem_base + (p ? SM_A1 : SM_A0);
#pragma unroll
        for (int split = 0; split < 3; split++) {
            uint32_t Abase = Ab + ((split < 2) ? 0 : A_LO_OFF);
            uint32_t Bbase = smem_base + ((split == 1) ? SM_BLO : SM_BHI);
#pragma unroll
            for (int kt = 0; kt < 8; kt++) {
                uint32_t bb[4][4];
#pragma unroll
                for (int pi = 0; pi < 4; pi++) {
                    int n0 = ng * 32 + ((pi & 1) ? 16 : 0) + ((pi & 2) ? 64 : 0);
                    int rowB = n0 + rowB_add;
                    uint32_t addr = Bbase + rowB * 256 + (uint32_t)((((2 * kt + chB) ^ (rowB & 7))) << 4);
                    ldsm4(bb[pi], addr);
                }
#pragma unroll
                for (int mt2 = 0; mt2 < 2; mt2++) {
                    uint32_t aa[4];
                    uint32_t addrA = Abase + rowA_off + (uint32_t)(mt2 * 16 * A_PITCH)
                                   + (uint32_t)((2 * kt + chA) << 4);
                    ldsm4(aa, addrA);
#pragma unroll
                    for (int pi = 0; pi < 4; pi++) {
                        mma16816(d[mt2][2 * pi],     aa, &bb[pi][0]);
                        mma16816(d[mt2][2 * pi + 1], aa, &bb[pi][2]);
                    }
                }
            }
        }

        // ---- epilogue: v = 0.5*(tanh(e12)+tanh(e21)); n-slots 0-3 = e12, 4-7 = e21
        float msum[4][2];
#pragma unroll
        for (int j = 0; j < 4; j++) { msum[j][0] = 0.0f; msum[j][1] = 0.0f; }

#pragma unroll
        for (int mt2 = 0; mt2 < 2; mt2++) {
            int rl0 = mg * 32 + mt2 * 16 + (lane >> 2);
            int rl1 = rl0 + 8;
            bool val0 = (t0 + rl0) < cnt;
            bool val1 = (t0 + rl1) < cnt;
            int ae0 = s_ae[p * 128 + rl0];
            int ae1 = s_ae[p * 128 + rl1];
            float* o0 = out_policy + ((size_t)b * EE + ae0) * DD;
            float* o1 = out_policy + ((size_t)b * EE + ae1) * DD;
#pragma unroll
            for (int j = 0; j < 4; j++) {
                const float* sD = d[mt2][j];
                const float* tD = d[mt2][4 + j];
                float v00 = 0.5f * (ftanh(sD[0] + ber[j][0]) + ftanh(tD[0] + ber[j][0]));
                float v01 = 0.5f * (ftanh(sD[1] + ber[j][1]) + ftanh(tD[1] + ber[j][1]));
                float v10 = 0.5f * (ftanh(sD[2] + ber[j][0]) + ftanh(tD[2] + ber[j][0]));
                float v11 = 0.5f * (ftanh(sD[3] + ber[j][1]) + ftanh(tD[3] + ber[j][1]));
                if (!val0) { v00 = 0.0f; v01 = 0.0f; }
                if (!val1) { v10 = 0.0f; v11 = 0.0f; }
                int cb = ng * 32 + 8 * j + 2 * (lane & 3);
                if (val0) *(float2*)(o0 + cb) = make_float2(v00, v01);
                if (val1) *(float2*)(o1 + cb) = make_float2(v10, v11);
                msum[j][0] += v00 + v10;
                msum[j][1] += v01 + v11;
            }
        }
#pragma unroll
        for (int j = 0; j < 4; j++) {
#pragma unroll
            for (int i = 0; i < 2; i++) {
                float v = msum[j][i];
                v += __shfl_xor_sync(0xffffffffu, v, 4);
                v += __shfl_xor_sync(0xffffffffu, v, 8);
                v += __shfl_xor_sync(0xffffffffu, v, 16);
                msum[j][i] = v;
            }
        }
        if (lane < 4) {
#pragma unroll
            for (int j = 0; j < 4; j++) {
                int c = ng * 32 + 8 * j + 2 * lane;
                atomicAdd(&s_sum[b * DD + c],     msum[j][0]);
                atomicAdd(&s_sum[b * DD + c + 1], msum[j][1]);
            }
        }

        __syncthreads();    // all compute on buffer p done before it is refilled
        p ^= 1;
    }

    __syncthreads();
    if (tid < 128) atomicAdd(&g_sum[tid], s_sum[tid]);
}

// -------- finalize --------
__global__ void k_final(const float* __restrict__ numerical,
                        const float* __restrict__ stage,
                        const float* __restrict__ W1, const float* __restrict__ b1,
                        const float* __restrict__ W2, const float* __restrict__ b2,
                        float* __restrict__ out_value)
{
    __shared__ float t1[BB * H0];
    __shared__ float part[BB * H1];
    int t = threadIdx.x;
    if (t < BB * H0) {
        int b = t / H0, j = t % H0;
        float acc = b1[j];
#pragma unroll
        for (int k = 0; k < NODE_DIM; k++) acc = fmaf(numerical[b * NODE_DIM + k], W1[k * H0 + j], acc);
        t1[t] = ftanh(acc);
    }
    __syncthreads();
    {
        int th = t >> 7;
        int o  = t & 127;
        int b = o / H1, j = o % H1;
        float acc = 0.0f;
#pragma unroll 8
        for (int k = th * 64; k < th * 64 + 64; k++)
            acc = fmaf(t1[b * H0 + k], W2[k * H1 + j], acc);
        if (th == 1) part[o] = acc;
        __syncthreads();
        if (th == 0) {
            float s = acc + part[o] + b2[j];
            out_value[b * 130 + j] = ftanh(s);
            out_value[b * 130 + 64 + j] = g_sum[b * DD + j] / (float)g_cnt[b];
        }
    }
    if (t < BB * 2) {
        int b = t >> 1, s2 = t & 1;
        out_value[b * 130 + 128 + s2] = stage[b * 2 + s2];
    }
}

// -------- launch --------
extern "C" void kernel_launch(void* const* d_in, const int* in_sizes, int n_in,
                              void* d_out, int out_size) {
    (void)in_sizes; (void)n_in; (void)out_size;
    const float* numerical    = (const float*)d_in[0];
    const float* node_feature = (const float*)d_in[1];
    const int*   edge_index   = (const int*)d_in[2];
    const void*  edge_mask    = d_in[3];
    const float* stage        = (const float*)d_in[4];
    const float* W1 = (const float*)d_in[5];
    const float* b1 = (const float*)d_in[6];
    const float* W2 = (const float*)d_in[7];
    const float* b2 = (const float*)d_in[8];
    const float* Wn = (const float*)d_in[9];
    const float* bn = (const float*)d_in[10];
    const float* We = (const float*)d_in[11];
    const float* be = (const float*)d_in[12];

    float* out        = (float*)d_out;
    float* out_policy = out;
    float* out_value  = out + (size_t)BB * EE * DD;

    cudaFuncSetAttribute(k_edges, cudaFuncAttributeMaxDynamicSharedMemorySize, EDGE_SMEM);

    k_init <<<1, 256>>>((const unsigned int*)edge_mask);
    k_cntA <<<250, 128>>>(edge_mask);
    k_scanB<<<1, 1024>>>();
    k_scatC<<<250, 128>>>(edge_mask);
    k_zero <<<12500, 256>>>(edge_mask, out_policy);
    k_nodes<<<2960, 256>>>(node_feature, Wn, bn);
    k_edges<<<148, 256, EDGE_SMEM>>>(We, be, edge_index, out_policy);
    k_final<<<1, 256>>>(numerical, stage, W1, b1, W2, b2, out_value);
}